// round 6
// baseline (speedup 1.0000x reference)
#include <cuda_runtime.h>
#include <cstdint>
#include <math.h>

// ---------------------------------------------------------------- constants
constexpr int B_   = 32;
constexpr int H_   = 56;
constexpr int W_   = 56;
constexpr int C_   = 192;
constexpr int NH_  = 6;
constexpr int WS_  = 7;
constexpr int SS_  = 3;
constexpr int N_   = 49;
constexpr int HD_  = 32;
constexpr int NWH  = 8;
constexpr int NW_  = 64;
constexpr int HID_ = 768;
constexpr int TOK  = B_ * H_ * W_;   // 100352
constexpr int WINS = B_ * NW_;       // 2048
constexpr int C3   = 3 * C_;         // 576

// GEMM tiling (mma.sync m16n8k8 tf32): 128x192 CTA tile, 64x48 warp tile
constexpr int BM = 128;
constexpr int BN = 192;
constexpr int BK = 16;
constexpr int APITCH = 20;    // BK + 4 pad  (20 mod 32 = 4 -> conflict-free frags)
constexpr int BPITCH = 200;   // BN + 8 pad  (200 mod 32 = 8 -> conflict-free frags)

// ---------------------------------------------------------------- scratch
__device__ float g_hwin[(size_t)TOK * C_];
__device__ float g_qkv[(size_t)TOK * C3];
__device__ float g_attno[(size_t)TOK * C_];
__device__ float g_x1[(size_t)TOK * C_];
__device__ float g_ln2[(size_t)TOK * C_];
__device__ float g_hid[(size_t)TOK * HID_];

// ---------------------------------------------------------------- helpers
__device__ __forceinline__ uint32_t smem_u32(const void* p) {
    uint32_t a;
    asm("{ .reg .u64 t; cvta.to.shared.u64 t, %1; cvt.u32.u64 %0, t; }"
        : "=r"(a) : "l"(p));
    return a;
}
#define CP_ASYNC16(dst_u32, src_ptr) \
    asm volatile("cp.async.ca.shared.global [%0], [%1], 16;" \
        :: "r"(dst_u32), "l"(src_ptr) : "memory")
#define CP_ASYNC_COMMIT() asm volatile("cp.async.commit_group;" ::: "memory")
#define CP_ASYNC_WAIT_1() asm volatile("cp.async.wait_group 1;" ::: "memory")
#define CP_ASYNC_WAIT_0() asm volatile("cp.async.wait_group 0;" ::: "memory")

__device__ __forceinline__ void mma_tf32(
    float* d, const uint32_t* a, const uint32_t* b)
{
    asm volatile(
        "mma.sync.aligned.m16n8k8.row.col.f32.tf32.tf32.f32 "
        "{%0,%1,%2,%3}, {%4,%5,%6,%7}, {%8,%9}, {%0,%1,%2,%3};"
        : "+f"(d[0]), "+f"(d[1]), "+f"(d[2]), "+f"(d[3])
        : "r"(a[0]), "r"(a[1]), "r"(a[2]), "r"(a[3]),
          "r"(b[0]), "r"(b[1]));
}

// ---------------------------------------------------------------- LayerNorm
template <int PART>
__global__ void __launch_bounds__(256) ln_kernel(
    const float* __restrict__ src, float* __restrict__ dst,
    const float* __restrict__ gamma, const float* __restrict__ beta)
{
    int warp = threadIdx.x >> 5;
    int lane = threadIdx.x & 31;
    int t = blockIdx.x * 8 + warp;
    if (t >= TOK) return;

    const float* xr = src + (size_t)t * C_;
    float v[6];
    float s = 0.f;
#pragma unroll
    for (int i = 0; i < 6; i++) { v[i] = xr[lane + 32 * i]; s += v[i]; }
#pragma unroll
    for (int o = 16; o; o >>= 1) s += __shfl_xor_sync(0xffffffffu, s, o);
    float mean = s * (1.f / 192.f);
    float ss = 0.f;
#pragma unroll
    for (int i = 0; i < 6; i++) { float d = v[i] - mean; ss += d * d; }
#pragma unroll
    for (int o = 16; o; o >>= 1) ss += __shfl_xor_sync(0xffffffffu, ss, o);
    float rstd = rsqrtf(ss * (1.f / 192.f) + 1e-5f);

    int dt = t;
    if (PART) {
        int bb = t / (H_ * W_);
        int rem = t - bb * (H_ * W_);
        int h = rem / W_, w = rem - (rem / W_) * W_;
        int hs = h - SS_; if (hs < 0) hs += H_;
        int ws = w - SS_; if (ws < 0) ws += W_;
        int wl = (hs / WS_) * NWH + (ws / WS_);
        int n  = (hs % WS_) * WS_ + (ws % WS_);
        dt = bb * (NW_ * N_) + wl * N_ + n;
    }
    float* o = dst + (size_t)dt * C_;
#pragma unroll
    for (int i = 0; i < 6; i++) {
        int c = lane + 32 * i;
        o[c] = (v[i] - mean) * rstd * gamma[c] + beta[c];
    }
}

// ---------------------------------------------------------------- mma GEMM
// C[M,N] = A[M,K] @ B[K,N]; 8 warps in 2(m) x 4(n), warp tile 64x48.
// EPI 0: +bias   EPI 1: +bias +window-reverse scatter +residual
// EPI 2: gelu(+bias)   EPI 3: +bias +residual
template <int EPI>
__global__ void __launch_bounds__(256, 1) gemm_mma(
    const float* __restrict__ A, const float* __restrict__ Bw,
    const float* __restrict__ bias, const float* __restrict__ add,
    float* __restrict__ Cout, int M, int N, int K)
{
    __shared__ __align__(16) float Asb[2][BM * APITCH];   // 20.5 KB
    __shared__ __align__(16) float Bsb[2][BK * BPITCH];   // 25.6 KB

    const int tid  = threadIdx.x;
    const int wid  = tid >> 5;
    const int lane = tid & 31;
    const int wm   = wid >> 2;          // 0..1
    const int wn   = wid & 3;           // 0..3
    const int lr   = lane >> 2;         // 0..7
    const int lc   = lane & 3;          // 0..3
    const int bm   = blockIdx.x * BM;
    const int bn   = blockIdx.y * BN;
    const int nk   = K / BK;

    float acc[4][6][4];
#pragma unroll
    for (int i = 0; i < 4; i++)
#pragma unroll
        for (int j = 0; j < 6; j++)
#pragma unroll
            for (int q = 0; q < 4; q++) acc[i][j][q] = 0.f;

    uint32_t asb = smem_u32(&Asb[0][0]);
    uint32_t bsb = smem_u32(&Bsb[0][0]);

    auto load_tile = [&](int k0, int st) {
        // A: 128 rows x 16 k = 512 float4
#pragma unroll
        for (int i = tid; i < 512; i += 256) {
            int m  = i >> 2;
            int k4 = i & 3;
            const float* src = A + (size_t)(bm + m) * K + k0 * BK + k4 * 4;
            uint32_t dst = asb + (uint32_t)(st * BM * APITCH + m * APITCH + k4 * 4) * 4;
            CP_ASYNC16(dst, src);
        }
        // B: 16 rows x 192 n = 768 float4
#pragma unroll
        for (int i = tid; i < 768; i += 256) {
            int k  = i / 48;
            int n4 = i - k * 48;
            const float* src = Bw + (size_t)(k0 * BK + k) * N + bn + n4 * 4;
            uint32_t dst = bsb + (uint32_t)(st * BK * BPITCH + k * BPITCH + n4 * 4) * 4;
            CP_ASYNC16(dst, src);
        }
        CP_ASYNC_COMMIT();
    };

    load_tile(0, 0);

    for (int k0 = 0; k0 < nk; k0++) {
        if (k0 + 1 < nk) { load_tile(k0 + 1, (k0 + 1) & 1); CP_ASYNC_WAIT_1(); }
        else             { CP_ASYNC_WAIT_0(); }
        __syncthreads();

        const float* As = Asb[k0 & 1];
        const float* Bs = Bsb[k0 & 1];
#pragma unroll
        for (int ks = 0; ks < 2; ks++) {
            int kk = ks * 8 + lc;
            uint32_t a[4][4];
#pragma unroll
            for (int mi = 0; mi < 4; mi++) {
                int m = wm * 64 + mi * 16 + lr;
                a[mi][0] = __float_as_uint(As[m * APITCH + kk]);
                a[mi][1] = __float_as_uint(As[(m + 8) * APITCH + kk]);
                a[mi][2] = __float_as_uint(As[m * APITCH + kk + 4]);
                a[mi][3] = __float_as_uint(As[(m + 8) * APITCH + kk + 4]);
            }
            uint32_t b[6][2];
#pragma unroll
            for (int ni = 0; ni < 6; ni++) {
                int n = wn * 48 + ni * 8 + lr;
                b[ni][0] = __float_as_uint(Bs[(ks * 8 + lc) * BPITCH + n]);
                b[ni][1] = __float_as_uint(Bs[(ks * 8 + lc + 4) * BPITCH + n]);
            }
#pragma unroll
            for (int mi = 0; mi < 4; mi++)
#pragma unroll
                for (int ni = 0; ni < 6; ni++)
                    mma_tf32(acc[mi][ni], a[mi], b[ni]);
        }
        __syncthreads();
    }

#pragma unroll
    for (int mi = 0; mi < 4; mi++) {
#pragma unroll
        for (int half = 0; half < 2; half++) {
            int row = bm + wm * 64 + mi * 16 + lr + half * 8;
            int orow = row;
            if (EPI == 1) {
                int win = row / N_, n = row - win * N_;
                int b = win >> 6, wl = win & 63;
                int hs = (wl >> 3) * WS_ + n / WS_;
                int ws = (wl & 7) * WS_ + (n - (n / WS_) * WS_);
                int h = hs + SS_; if (h >= H_) h -= H_;
                int w = ws + SS_; if (w >= W_) w -= W_;
                orow = (b * H_ + h) * W_ + w;
            }
#pragma unroll
            for (int ni = 0; ni < 6; ni++) {
                int c = bn + wn * 48 + ni * 8 + 2 * lc;
                float2 bv = *(const float2*)(bias + c);
                float vx = acc[mi][ni][half * 2 + 0] + bv.x;
                float vy = acc[mi][ni][half * 2 + 1] + bv.y;
                if (EPI == 1) {
                    float2 av = *(const float2*)(add + (size_t)orow * N + c);
                    vx += av.x; vy += av.y;
                }
                if (EPI == 2) { vx *= normcdff(vx); vy *= normcdff(vy); }
                if (EPI == 3) {
                    float2 av = *(const float2*)(add + (size_t)row * N + c);
                    vx += av.x; vy += av.y;
                }
                *(float2*)(Cout + (size_t)orow * N + c) = make_float2(vx, vy);
            }
        }
    }
}

// ---------------------------------------------------------------- attention
__global__ void __launch_bounds__(128) attn_kernel(
    const float* __restrict__ rpb, const float* __restrict__ mask)
{
    int win  = blockIdx.x;
    int head = blockIdx.y;
    int tid  = threadIdx.x;

    __shared__ __align__(16) float qs[N_][34];
    __shared__ __align__(16) float kT[HD_][50];
    __shared__ __align__(16) float vs[N_][HD_];
    __shared__ __align__(16) float sc[N_][50];
    __shared__ __align__(16) float rpbs[169];

    const float* base = g_qkv + (size_t)win * N_ * C3 + head * HD_;
    const float scale = 0.17677669529663687f;

    for (int idx = tid; idx < N_ * HD_; idx += 128) {
        int n = idx >> 5, d = idx & 31;
        const float* row = base + (size_t)n * C3 + d;
        qs[n][d] = row[0] * scale;
        kT[d][n] = row[C_];
        vs[n][d] = row[2 * C_];
    }
    for (int idx = tid; idx < 169; idx += 128)
        rpbs[idx] = rpb[idx * NH_ + head];
    __syncthreads();

    const float* mrow = mask + (size_t)(win & (NW_ - 1)) * N_ * N_;
    for (int cell = tid; cell < 175; cell += 128) {
        int ng = cell / 25;
        int m2 = cell - ng * 25;
        int m  = m2 * 2;
        float acc[7][2];
#pragma unroll
        for (int j = 0; j < 7; j++) { acc[j][0] = 0.f; acc[j][1] = 0.f; }
#pragma unroll
        for (int d = 0; d < HD_; d += 2) {
            float2 k0 = *(const float2*)&kT[d][m];
            float2 k1 = *(const float2*)&kT[d + 1][m];
#pragma unroll
            for (int j = 0; j < 7; j++) {
                float2 qv = *(const float2*)&qs[ng * 7 + j][d];
                acc[j][0] += qv.x * k0.x + qv.y * k1.x;
                acc[j][1] += qv.x * k0.y + qv.y * k1.y;
            }
        }
        int i2 = m / WS_, j2 = m - i2 * WS_;
        int i2b = (m + 1) / WS_, j2b = (m + 1) - i2b * WS_;
#pragma unroll
        for (int j = 0; j < 7; j++) {
            int n = ng * 7 + j;
            int i1 = n / WS_, j1 = n - i1 * WS_;
            int rel0 = (i1 - i2 + WS_ - 1) * (2 * WS_ - 1) + (j1 - j2 + WS_ - 1);
            sc[n][m] = acc[j][0] + rpbs[rel0] + mrow[n * N_ + m];
            if (m + 1 < N_) {
                int rel1 = (i1 - i2b + WS_ - 1) * (2 * WS_ - 1) + (j1 - j2b + WS_ - 1);
                sc[n][m + 1] = acc[j][1] + rpbs[rel1] + mrow[n * N_ + m + 1];
            }
        }
    }
    __syncthreads();

    int warp = tid >> 5, lane = tid & 31;
    for (int n = warp; n < N_; n += 4) {
        float v0 = (lane < N_)      ? sc[n][lane]      : -1e30f;
        float v1 = (lane + 32 < N_) ? sc[n][lane + 32] : -1e30f;
        float mx = fmaxf(v0, v1);
#pragma unroll
        for (int o = 16; o; o >>= 1) mx = fmaxf(mx, __shfl_xor_sync(0xffffffffu, mx, o));
        float e0 = (lane < N_)      ? __expf(v0 - mx) : 0.f;
        float e1 = (lane + 32 < N_) ? __expf(v1 - mx) : 0.f;
        float s = e0 + e1;
#pragma unroll
        for (int o = 16; o; o >>= 1) s += __shfl_xor_sync(0xffffffffu, s, o);
        float inv = 1.f / s;
        if (lane < N_)      sc[n][lane]      = e0 * inv;
        if (lane + 32 < N_) sc[n][lane + 32] = e1 * inv;
    }
    __syncthreads();

    if (tid < 104) {
        int ngb = tid >> 3;
        int d   = (tid & 7) * 4;
        float acc[4][4];
#pragma unroll
        for (int i = 0; i < 4; i++)
#pragma unroll
            for (int q = 0; q < 4; q++) acc[i][q] = 0.f;

        for (int m = 0; m < N_; m++) {
            float4 vv = *(const float4*)&vs[m][d];
#pragma unroll
            for (int i = 0; i < 4; i++) {
                int n = ngb * 4 + i;
                float p = (n < N_) ? sc[n][m] : 0.f;
                acc[i][0] += p * vv.x;
                acc[i][1] += p * vv.y;
                acc[i][2] += p * vv.z;
                acc[i][3] += p * vv.w;
            }
        }
        float* ob = g_attno + (size_t)win * N_ * C_ + head * HD_;
#pragma unroll
        for (int i = 0; i < 4; i++) {
            int n = ngb * 4 + i;
            if (n < N_)
                *(float4*)(ob + (size_t)n * C_ + d) =
                    make_float4(acc[i][0], acc[i][1], acc[i][2], acc[i][3]);
        }
    }
}

// ----------------------------------------------------------------
extern "C" void kernel_launch(void* const* d_in, const int* in_sizes, int n_in,
                              void* d_out, int out_size)
{
    const float* x     = (const float*)d_in[0];
    const float* mask  = (const float*)d_in[1];
    const float* ln1g  = (const float*)d_in[2];
    const float* ln1b  = (const float*)d_in[3];
    const float* qkvw  = (const float*)d_in[4];
    const float* qkvb  = (const float*)d_in[5];
    const float* rpb   = (const float*)d_in[6];
    const float* projw = (const float*)d_in[7];
    const float* projb = (const float*)d_in[8];
    const float* ln2g  = (const float*)d_in[9];
    const float* ln2b  = (const float*)d_in[10];
    const float* fc1w  = (const float*)d_in[11];
    const float* fc1b  = (const float*)d_in[12];
    const float* fc2w  = (const float*)d_in[13];
    const float* fc2b  = (const float*)d_in[14];
    float* out = (float*)d_out;

    float *hwin, *qkv, *attno, *x1, *ln2, *hid;
    cudaGetSymbolAddress((void**)&hwin,  g_hwin);
    cudaGetSymbolAddress((void**)&qkv,   g_qkv);
    cudaGetSymbolAddress((void**)&attno, g_attno);
    cudaGetSymbolAddress((void**)&x1,    g_x1);
    cudaGetSymbolAddress((void**)&ln2,   g_ln2);
    cudaGetSymbolAddress((void**)&hid,   g_hid);

    const int ln_grid = TOK / 8;

    // 1) LN1 + shift + window partition
    ln_kernel<1><<<ln_grid, 256>>>(x, hwin, ln1g, ln1b);

    // 2) QKV GEMM
    gemm_mma<0><<<dim3(TOK / BM, C3 / BN), 256>>>(
        hwin, qkvw, qkvb, nullptr, qkv, TOK, C3, C_);

    // 3) Windowed attention
    attn_kernel<<<dim3(WINS, NH_), 128>>>(rpb, mask);

    // 4) proj + window reverse + residual -> x1
    gemm_mma<1><<<dim3(TOK / BM, C_ / BN), 256>>>(
        attno, projw, projb, x, x1, TOK, C_, C_);

    // 5) LN2
    ln_kernel<0><<<ln_grid, 256>>>(x1, ln2, ln2g, ln2b);

    // 6) FC1 + GELU
    gemm_mma<2><<<dim3(TOK / BM, HID_ / BN), 256>>>(
        ln2, fc1w, fc1b, nullptr, hid, TOK, HID_, C_);

    // 7) FC2 + residual -> out
    gemm_mma<3><<<dim3(TOK / BM, C_ / BN), 256>>>(
        hid, fc2w, fc2b, x1, out, TOK, C_, HID_);
}

// round 7
// speedup vs baseline: 1.1451x; 1.1451x over previous
#include <cuda_runtime.h>
#include <cstdint>
#include <math.h>

// ---------------------------------------------------------------- constants
constexpr int B_   = 32;
constexpr int H_   = 56;
constexpr int W_   = 56;
constexpr int C_   = 192;
constexpr int NH_  = 6;
constexpr int WS_  = 7;
constexpr int SS_  = 3;
constexpr int N_   = 49;
constexpr int HD_  = 32;
constexpr int NWH  = 8;
constexpr int NW_  = 64;
constexpr int HID_ = 768;
constexpr int TOK  = B_ * H_ * W_;   // 100352
constexpr int WINS = B_ * NW_;       // 2048
constexpr int C3   = 3 * C_;         // 576

// GEMM tiling (mma.sync m16n8k8 tf32): 128x96 CTA tile, 64x24 warp tile, BK=32
constexpr int BM = 128;
constexpr int BN = 96;
constexpr int BK = 32;
constexpr int APITCH = 36;    // BK + 4 pad  (36 mod 32 = 4 -> conflict-free frags)
constexpr int BPITCH = 104;   // BN + 8 pad  (104 mod 32 = 8 -> conflict-free frags)

constexpr int A_STAGE = BM * APITCH;          // 4608 floats
constexpr int B_STAGE = BK * BPITCH;          // 3328 floats
constexpr int SMEM_FLOATS = 2 * A_STAGE + 2 * B_STAGE;   // 15872
constexpr int SMEM_BYTES  = SMEM_FLOATS * 4;             // 63488

// ---------------------------------------------------------------- scratch
__device__ float g_hwin[(size_t)TOK * C_];
__device__ float g_qkv[(size_t)TOK * C3];
__device__ float g_attno[(size_t)TOK * C_];
__device__ float g_x1[(size_t)TOK * C_];
__device__ float g_ln2[(size_t)TOK * C_];
__device__ float g_hid[(size_t)TOK * HID_];

// ---------------------------------------------------------------- helpers
__device__ __forceinline__ uint32_t smem_u32(const void* p) {
    uint32_t a;
    asm("{ .reg .u64 t; cvta.to.shared.u64 t, %1; cvt.u32.u64 %0, t; }"
        : "=r"(a) : "l"(p));
    return a;
}
#define CP_ASYNC16(dst_u32, src_ptr) \
    asm volatile("cp.async.ca.shared.global [%0], [%1], 16;" \
        :: "r"(dst_u32), "l"(src_ptr) : "memory")
#define CP_ASYNC_COMMIT() asm volatile("cp.async.commit_group;" ::: "memory")
#define CP_ASYNC_WAIT_1() asm volatile("cp.async.wait_group 1;" ::: "memory")
#define CP_ASYNC_WAIT_0() asm volatile("cp.async.wait_group 0;" ::: "memory")

__device__ __forceinline__ void mma_tf32(
    float* d, const uint32_t* a, const uint32_t* b)
{
    asm volatile(
        "mma.sync.aligned.m16n8k8.row.col.f32.tf32.tf32.f32 "
        "{%0,%1,%2,%3}, {%4,%5,%6,%7}, {%8,%9}, {%0,%1,%2,%3};"
        : "+f"(d[0]), "+f"(d[1]), "+f"(d[2]), "+f"(d[3])
        : "r"(a[0]), "r"(a[1]), "r"(a[2]), "r"(a[3]),
          "r"(b[0]), "r"(b[1]));
}

// ---------------------------------------------------------------- LayerNorm
template <int PART>
__global__ void __launch_bounds__(256) ln_kernel(
    const float* __restrict__ src, float* __restrict__ dst,
    const float* __restrict__ gamma, const float* __restrict__ beta)
{
    int warp = threadIdx.x >> 5;
    int lane = threadIdx.x & 31;
    int t = blockIdx.x * 8 + warp;
    if (t >= TOK) return;

    const float* xr = src + (size_t)t * C_;
    float v[6];
    float s = 0.f;
#pragma unroll
    for (int i = 0; i < 6; i++) { v[i] = xr[lane + 32 * i]; s += v[i]; }
#pragma unroll
    for (int o = 16; o; o >>= 1) s += __shfl_xor_sync(0xffffffffu, s, o);
    float mean = s * (1.f / 192.f);
    float ss = 0.f;
#pragma unroll
    for (int i = 0; i < 6; i++) { float d = v[i] - mean; ss += d * d; }
#pragma unroll
    for (int o = 16; o; o >>= 1) ss += __shfl_xor_sync(0xffffffffu, ss, o);
    float rstd = rsqrtf(ss * (1.f / 192.f) + 1e-5f);

    int dt = t;
    if (PART) {
        int bb = t / (H_ * W_);
        int rem = t - bb * (H_ * W_);
        int h = rem / W_, w = rem - (rem / W_) * W_;
        int hs = h - SS_; if (hs < 0) hs += H_;
        int ws = w - SS_; if (ws < 0) ws += W_;
        int wl = (hs / WS_) * NWH + (ws / WS_);
        int n  = (hs % WS_) * WS_ + (ws % WS_);
        dt = bb * (NW_ * N_) + wl * N_ + n;
    }
    float* o = dst + (size_t)dt * C_;
#pragma unroll
    for (int i = 0; i < 6; i++) {
        int c = lane + 32 * i;
        o[c] = (v[i] - mean) * rstd * gamma[c] + beta[c];
    }
}

// ---------------------------------------------------------------- mma GEMM
// C[M,N] = A[M,K] @ B[K,N]; 8 warps in 2(m) x 4(n), warp tile 64x24, BK=32.
// Dynamic smem (63.5KB), double-buffered cp.async pipeline.
// EPI 0: +bias   EPI 1: +bias +window-reverse scatter +residual
// EPI 2: gelu(+bias)   EPI 3: +bias +residual
template <int EPI>
__global__ void __launch_bounds__(256) gemm_mma(
    const float* __restrict__ A, const float* __restrict__ Bw,
    const float* __restrict__ bias, const float* __restrict__ add,
    float* __restrict__ Cout, int M, int N, int K)
{
    extern __shared__ __align__(16) float smem[];
    float* Asm = smem;                       // 2 stages of BM x APITCH
    float* Bsm = smem + 2 * A_STAGE;         // 2 stages of BK x BPITCH

    const int tid  = threadIdx.x;
    const int wid  = tid >> 5;
    const int lane = tid & 31;
    const int wm   = wid >> 2;          // 0..1
    const int wn   = wid & 3;           // 0..3
    const int lr   = lane >> 2;         // 0..7
    const int lc   = lane & 3;          // 0..3
    const int bm   = blockIdx.x * BM;
    const int bn   = blockIdx.y * BN;
    const int nk   = K / BK;

    float acc[4][3][4];
#pragma unroll
    for (int i = 0; i < 4; i++)
#pragma unroll
        for (int j = 0; j < 3; j++)
#pragma unroll
            for (int q = 0; q < 4; q++) acc[i][j][q] = 0.f;

    uint32_t asb = smem_u32(Asm);
    uint32_t bsb = smem_u32(Bsm);

    auto load_tile = [&](int k0, int st) {
        // A: 128 rows x 32 k = 1024 float4 (4 per thread)
#pragma unroll
        for (int i = tid; i < 1024; i += 256) {
            int m  = i >> 3;
            int k4 = i & 7;
            const float* src = A + (size_t)(bm + m) * K + k0 * BK + k4 * 4;
            uint32_t dst = asb + (uint32_t)(st * A_STAGE + m * APITCH + k4 * 4) * 4;
            CP_ASYNC16(dst, src);
        }
        // B: 32 rows x 96 n = 768 float4 (3 per thread)
#pragma unroll
        for (int i = tid; i < 768; i += 256) {
            int k  = i / 24;
            int n4 = i - k * 24;
            const float* src = Bw + (size_t)(k0 * BK + k) * N + bn + n4 * 4;
            uint32_t dst = bsb + (uint32_t)(st * B_STAGE + k * BPITCH + n4 * 4) * 4;
            CP_ASYNC16(dst, src);
        }
        CP_ASYNC_COMMIT();
    };

    load_tile(0, 0);

    for (int k0 = 0; k0 < nk; k0++) {
        if (k0 + 1 < nk) { load_tile(k0 + 1, (k0 + 1) & 1); CP_ASYNC_WAIT_1(); }
        else             { CP_ASYNC_WAIT_0(); }
        __syncthreads();

        const float* As = Asm + (k0 & 1) * A_STAGE;
        const float* Bs = Bsm + (k0 & 1) * B_STAGE;
#pragma unroll
        for (int ks = 0; ks < 4; ks++) {
            int kk = ks * 8 + lc;
            uint32_t a[4][4];
#pragma unroll
            for (int mi = 0; mi < 4; mi++) {
                int m = wm * 64 + mi * 16 + lr;
                a[mi][0] = __float_as_uint(As[m * APITCH + kk]);
                a[mi][1] = __float_as_uint(As[(m + 8) * APITCH + kk]);
                a[mi][2] = __float_as_uint(As[m * APITCH + kk + 4]);
                a[mi][3] = __float_as_uint(As[(m + 8) * APITCH + kk + 4]);
            }
            uint32_t b[3][2];
#pragma unroll
            for (int ni = 0; ni < 3; ni++) {
                int n = wn * 24 + ni * 8 + lr;
                b[ni][0] = __float_as_uint(Bs[(ks * 8 + lc) * BPITCH + n]);
                b[ni][1] = __float_as_uint(Bs[(ks * 8 + lc + 4) * BPITCH + n]);
            }
#pragma unroll
            for (int mi = 0; mi < 4; mi++)
#pragma unroll
                for (int ni = 0; ni < 3; ni++)
                    mma_tf32(acc[mi][ni], a[mi], b[ni]);
        }
        __syncthreads();
    }

#pragma unroll
    for (int mi = 0; mi < 4; mi++) {
#pragma unroll
        for (int half = 0; half < 2; half++) {
            int row = bm + wm * 64 + mi * 16 + lr + half * 8;
            int orow = row;
            if (EPI == 1) {
                int win = row / N_, n = row - win * N_;
                int b = win >> 6, wl = win & 63;
                int hs = (wl >> 3) * WS_ + n / WS_;
                int ws = (wl & 7) * WS_ + (n - (n / WS_) * WS_);
                int h = hs + SS_; if (h >= H_) h -= H_;
                int w = ws + SS_; if (w >= W_) w -= W_;
                orow = (b * H_ + h) * W_ + w;
            }
#pragma unroll
            for (int ni = 0; ni < 3; ni++) {
                int c = bn + wn * 24 + ni * 8 + 2 * lc;
                float2 bv = *(const float2*)(bias + c);
                float vx = acc[mi][ni][half * 2 + 0] + bv.x;
                float vy = acc[mi][ni][half * 2 + 1] + bv.y;
                if (EPI == 1) {
                    float2 av = *(const float2*)(add + (size_t)orow * N + c);
                    vx += av.x; vy += av.y;
                }
                if (EPI == 2) { vx *= normcdff(vx); vy *= normcdff(vy); }
                if (EPI == 3) {
                    float2 av = *(const float2*)(add + (size_t)row * N + c);
                    vx += av.x; vy += av.y;
                }
                *(float2*)(Cout + (size_t)orow * N + c) = make_float2(vx, vy);
            }
        }
    }
}

// ---------------------------------------------------------------- attention
__global__ void __launch_bounds__(128) attn_kernel(
    const float* __restrict__ rpb, const float* __restrict__ mask)
{
    int win  = blockIdx.x;
    int head = blockIdx.y;
    int tid  = threadIdx.x;

    __shared__ __align__(16) float qs[N_][34];
    __shared__ __align__(16) float kT[HD_][50];
    __shared__ __align__(16) float vs[N_][HD_];
    __shared__ __align__(16) float sc[N_][50];
    __shared__ __align__(16) float rpbs[169];

    const float* base = g_qkv + (size_t)win * N_ * C3 + head * HD_;
    const float scale = 0.17677669529663687f;

    for (int idx = tid; idx < N_ * HD_; idx += 128) {
        int n = idx >> 5, d = idx & 31;
        const float* row = base + (size_t)n * C3 + d;
        qs[n][d] = row[0] * scale;
        kT[d][n] = row[C_];
        vs[n][d] = row[2 * C_];
    }
    for (int idx = tid; idx < 169; idx += 128)
        rpbs[idx] = rpb[idx * NH_ + head];
    __syncthreads();

    const float* mrow = mask + (size_t)(win & (NW_ - 1)) * N_ * N_;
    for (int cell = tid; cell < 175; cell += 128) {
        int ng = cell / 25;
        int m2 = cell - ng * 25;
        int m  = m2 * 2;
        float acc[7][2];
#pragma unroll
        for (int j = 0; j < 7; j++) { acc[j][0] = 0.f; acc[j][1] = 0.f; }
#pragma unroll
        for (int d = 0; d < HD_; d += 2) {
            float2 k0 = *(const float2*)&kT[d][m];
            float2 k1 = *(const float2*)&kT[d + 1][m];
#pragma unroll
            for (int j = 0; j < 7; j++) {
                float2 qv = *(const float2*)&qs[ng * 7 + j][d];
                acc[j][0] += qv.x * k0.x + qv.y * k1.x;
                acc[j][1] += qv.x * k0.y + qv.y * k1.y;
            }
        }
        int i2 = m / WS_, j2 = m - i2 * WS_;
        int i2b = (m + 1) / WS_, j2b = (m + 1) - i2b * WS_;
#pragma unroll
        for (int j = 0; j < 7; j++) {
            int n = ng * 7 + j;
            int i1 = n / WS_, j1 = n - i1 * WS_;
            int rel0 = (i1 - i2 + WS_ - 1) * (2 * WS_ - 1) + (j1 - j2 + WS_ - 1);
            sc[n][m] = acc[j][0] + rpbs[rel0] + mrow[n * N_ + m];
            if (m + 1 < N_) {
                int rel1 = (i1 - i2b + WS_ - 1) * (2 * WS_ - 1) + (j1 - j2b + WS_ - 1);
                sc[n][m + 1] = acc[j][1] + rpbs[rel1] + mrow[n * N_ + m + 1];
            }
        }
    }
    __syncthreads();

    int warp = tid >> 5, lane = tid & 31;
    for (int n = warp; n < N_; n += 4) {
        float v0 = (lane < N_)      ? sc[n][lane]      : -1e30f;
        float v1 = (lane + 32 < N_) ? sc[n][lane + 32] : -1e30f;
        float mx = fmaxf(v0, v1);
#pragma unroll
        for (int o = 16; o; o >>= 1) mx = fmaxf(mx, __shfl_xor_sync(0xffffffffu, mx, o));
        float e0 = (lane < N_)      ? __expf(v0 - mx) : 0.f;
        float e1 = (lane + 32 < N_) ? __expf(v1 - mx) : 0.f;
        float s = e0 + e1;
#pragma unroll
        for (int o = 16; o; o >>= 1) s += __shfl_xor_sync(0xffffffffu, s, o);
        float inv = 1.f / s;
        if (lane < N_)      sc[n][lane]      = e0 * inv;
        if (lane + 32 < N_) sc[n][lane + 32] = e1 * inv;
    }
    __syncthreads();

    if (tid < 104) {
        int ngb = tid >> 3;
        int d   = (tid & 7) * 4;
        float acc[4][4];
#pragma unroll
        for (int i = 0; i < 4; i++)
#pragma unroll
            for (int q = 0; q < 4; q++) acc[i][q] = 0.f;

        for (int m = 0; m < N_; m++) {
            float4 vv = *(const float4*)&vs[m][d];
#pragma unroll
            for (int i = 0; i < 4; i++) {
                int n = ngb * 4 + i;
                float p = (n < N_) ? sc[n][m] : 0.f;
                acc[i][0] += p * vv.x;
                acc[i][1] += p * vv.y;
                acc[i][2] += p * vv.z;
                acc[i][3] += p * vv.w;
            }
        }
        float* ob = g_attno + (size_t)win * N_ * C_ + head * HD_;
#pragma unroll
        for (int i = 0; i < 4; i++) {
            int n = ngb * 4 + i;
            if (n < N_)
                *(float4*)(ob + (size_t)n * C_ + d) =
                    make_float4(acc[i][0], acc[i][1], acc[i][2], acc[i][3]);
        }
    }
}

// ----------------------------------------------------------------
extern "C" void kernel_launch(void* const* d_in, const int* in_sizes, int n_in,
                              void* d_out, int out_size)
{
    const float* x     = (const float*)d_in[0];
    const float* mask  = (const float*)d_in[1];
    const float* ln1g  = (const float*)d_in[2];
    const float* ln1b  = (const float*)d_in[3];
    const float* qkvw  = (const float*)d_in[4];
    const float* qkvb  = (const float*)d_in[5];
    const float* rpb   = (const float*)d_in[6];
    const float* projw = (const float*)d_in[7];
    const float* projb = (const float*)d_in[8];
    const float* ln2g  = (const float*)d_in[9];
    const float* ln2b  = (const float*)d_in[10];
    const float* fc1w  = (const float*)d_in[11];
    const float* fc1b  = (const float*)d_in[12];
    const float* fc2w  = (const float*)d_in[13];
    const float* fc2b  = (const float*)d_in[14];
    float* out = (float*)d_out;

    float *hwin, *qkv, *attno, *x1, *ln2, *hid;
    cudaGetSymbolAddress((void**)&hwin,  g_hwin);
    cudaGetSymbolAddress((void**)&qkv,   g_qkv);
    cudaGetSymbolAddress((void**)&attno, g_attno);
    cudaGetSymbolAddress((void**)&x1,    g_x1);
    cudaGetSymbolAddress((void**)&ln2,   g_ln2);
    cudaGetSymbolAddress((void**)&hid,   g_hid);

    // Dynamic smem opt-in (63.5KB > 48KB default). Host-side API, deterministic.
    cudaFuncSetAttribute(gemm_mma<0>, cudaFuncAttributeMaxDynamicSharedMemorySize, SMEM_BYTES);
    cudaFuncSetAttribute(gemm_mma<1>, cudaFuncAttributeMaxDynamicSharedMemorySize, SMEM_BYTES);
    cudaFuncSetAttribute(gemm_mma<2>, cudaFuncAttributeMaxDynamicSharedMemorySize, SMEM_BYTES);
    cudaFuncSetAttribute(gemm_mma<3>, cudaFuncAttributeMaxDynamicSharedMemorySize, SMEM_BYTES);

    const int ln_grid = TOK / 8;

    // 1) LN1 + shift + window partition
    ln_kernel<1><<<ln_grid, 256>>>(x, hwin, ln1g, ln1b);

    // 2) QKV GEMM
    gemm_mma<0><<<dim3(TOK / BM, C3 / BN), 256, SMEM_BYTES>>>(
        hwin, qkvw, qkvb, nullptr, qkv, TOK, C3, C_);

    // 3) Windowed attention
    attn_kernel<<<dim3(WINS, NH_), 128>>>(rpb, mask);

    // 4) proj + window reverse + residual -> x1
    gemm_mma<1><<<dim3(TOK / BM, C_ / BN), 256, SMEM_BYTES>>>(
        attno, projw, projb, x, x1, TOK, C_, C_);

    // 5) LN2
    ln_kernel<0><<<ln_grid, 256>>>(x1, ln2, ln2g, ln2b);

    // 6) FC1 + GELU
    gemm_mma<2><<<dim3(TOK / BM, HID_ / BN), 256, SMEM_BYTES>>>(
        ln2, fc1w, fc1b, nullptr, hid, TOK, HID_, C_);

    // 7) FC2 + residual -> out
    gemm_mma<3><<<dim3(TOK / BM, C_ / BN), 256, SMEM_BYTES>>>(
        hid, fc2w, fc2b, x1, out, TOK, C_, HID_);
}

// round 8
// speedup vs baseline: 1.5099x; 1.3185x over previous
#include <cuda_runtime.h>
#include <cuda_bf16.h>
#include <cstdint>
#include <math.h>

// ---------------------------------------------------------------- constants
constexpr int B_   = 32;
constexpr int H_   = 56;
constexpr int W_   = 56;
constexpr int C_   = 192;
constexpr int NH_  = 6;
constexpr int WS_  = 7;
constexpr int SS_  = 3;
constexpr int N_   = 49;
constexpr int HD_  = 32;
constexpr int NWH  = 8;
constexpr int NW_  = 64;
constexpr int HID_ = 768;
constexpr int TOK  = B_ * H_ * W_;   // 100352
constexpr int WINS = B_ * NW_;       // 2048
constexpr int C3   = 3 * C_;         // 576

// GEMM tiling (mma.sync m16n8k16 bf16): 128x96 CTA, 64x24 warp tile, BK=64
constexpr int BM = 128;
constexpr int BN = 96;
constexpr int BK = 64;               // bf16 elements = 128B per row
constexpr int PITCH = 72;            // bf16 units per smem row (64 + 8 pad)
constexpr int WPITCH = 36;           // 32-bit words per row
constexpr int A_STAGE = BM * PITCH;  // bf16 units
constexpr int B_STAGE = BN * PITCH;
constexpr int SMEM_BYTES = 2 * (A_STAGE + B_STAGE) * 2;   // 64512

// ---------------------------------------------------------------- scratch
__device__ __nv_bfloat16 g_hwin[(size_t)TOK * C_];
__device__ __nv_bfloat16 g_qkv[(size_t)TOK * C3];
__device__ __nv_bfloat16 g_attno[(size_t)TOK * C_];
__device__ float         g_x1[(size_t)TOK * C_];
__device__ __nv_bfloat16 g_ln2[(size_t)TOK * C_];
__device__ __nv_bfloat16 g_hid[(size_t)TOK * HID_];
// weights, converted to bf16 and transposed to [N][K]
__device__ __nv_bfloat16 g_qkvwT[(size_t)C3 * C_];
__device__ __nv_bfloat16 g_projT[(size_t)C_ * C_];
__device__ __nv_bfloat16 g_fc1T[(size_t)HID_ * C_];
__device__ __nv_bfloat16 g_fc2T[(size_t)C_ * HID_];

// ---------------------------------------------------------------- helpers
__device__ __forceinline__ uint32_t smem_u32(const void* p) {
    uint32_t a;
    asm("{ .reg .u64 t; cvta.to.shared.u64 t, %1; cvt.u32.u64 %0, t; }"
        : "=r"(a) : "l"(p));
    return a;
}
#define CP_ASYNC16(dst_u32, src_ptr) \
    asm volatile("cp.async.ca.shared.global [%0], [%1], 16;" \
        :: "r"(dst_u32), "l"(src_ptr) : "memory")
#define CP_ASYNC_COMMIT() asm volatile("cp.async.commit_group;" ::: "memory")
#define CP_ASYNC_WAIT_1() asm volatile("cp.async.wait_group 1;" ::: "memory")
#define CP_ASYNC_WAIT_0() asm volatile("cp.async.wait_group 0;" ::: "memory")

__device__ __forceinline__ void mma_bf16(
    float* d, const uint32_t* a, const uint32_t* b)
{
    asm volatile(
        "mma.sync.aligned.m16n8k16.row.col.f32.bf16.bf16.f32 "
        "{%0,%1,%2,%3}, {%4,%5,%6,%7}, {%8,%9}, {%0,%1,%2,%3};"
        : "+f"(d[0]), "+f"(d[1]), "+f"(d[2]), "+f"(d[3])
        : "r"(a[0]), "r"(a[1]), "r"(a[2]), "r"(a[3]),
          "r"(b[0]), "r"(b[1]));
}

// --------------------------------------------- weight convert + transpose
// src fp32 [K][N] -> dst bf16 [N][K]
__global__ void wprep_kernel(const float* __restrict__ src,
                             __nv_bfloat16* __restrict__ dst, int K, int N)
{
    __shared__ float t[32][33];
    int kb = blockIdx.x * 32, nb = blockIdx.y * 32;
    int x = threadIdx.x, y = threadIdx.y;      // 32 x 8
    for (int i = y; i < 32; i += 8)
        t[i][x] = src[(size_t)(kb + i) * N + nb + x];
    __syncthreads();
    for (int i = y; i < 32; i += 8)
        dst[(size_t)(nb + i) * K + kb + x] = __float2bfloat16_rn(t[x][i]);
}

// ---------------------------------------------------------------- LayerNorm
// PART=1: + cyclic shift + window partition. Output bf16.
template <int PART>
__global__ void __launch_bounds__(256) ln_kernel(
    const float* __restrict__ src, __nv_bfloat16* __restrict__ dst,
    const float* __restrict__ gamma, const float* __restrict__ beta)
{
    int warp = threadIdx.x >> 5;
    int lane = threadIdx.x & 31;
    int t = blockIdx.x * 8 + warp;
    if (t >= TOK) return;

    const float* xr = src + (size_t)t * C_;
    float v[6];
    float s = 0.f;
#pragma unroll
    for (int i = 0; i < 6; i++) { v[i] = xr[lane + 32 * i]; s += v[i]; }
#pragma unroll
    for (int o = 16; o; o >>= 1) s += __shfl_xor_sync(0xffffffffu, s, o);
    float mean = s * (1.f / 192.f);
    float ss = 0.f;
#pragma unroll
    for (int i = 0; i < 6; i++) { float d = v[i] - mean; ss += d * d; }
#pragma unroll
    for (int o = 16; o; o >>= 1) ss += __shfl_xor_sync(0xffffffffu, ss, o);
    float rstd = rsqrtf(ss * (1.f / 192.f) + 1e-5f);

    int dt = t;
    if (PART) {
        int bb = t / (H_ * W_);
        int rem = t - bb * (H_ * W_);
        int h = rem / W_, w = rem - (rem / W_) * W_;
        int hs = h - SS_; if (hs < 0) hs += H_;
        int ws = w - SS_; if (ws < 0) ws += W_;
        int wl = (hs / WS_) * NWH + (ws / WS_);
        int n  = (hs % WS_) * WS_ + (ws % WS_);
        dt = bb * (NW_ * N_) + wl * N_ + n;
    }
    __nv_bfloat16* o = dst + (size_t)dt * C_;
#pragma unroll
    for (int i = 0; i < 6; i++) {
        int c = lane + 32 * i;
        o[c] = __float2bfloat16_rn((v[i] - mean) * rstd * gamma[c] + beta[c]);
    }
}

// ---------------------------------------------------------------- bf16 GEMM
// C[M,N] = A[M,K](bf16) @ Bt[N,K](bf16)^T ; fp32 accum.
// 8 warps 2(m)x4(n), warp tile 64x24, BK=64, double-buffered cp.async.
// EPI 0: +bias -> bf16 (qkv)
// EPI 1: +bias +window-reverse scatter +fp32 residual -> fp32 (proj->x1)
// EPI 2: gelu(+bias) -> bf16 (fc1)
// EPI 3: +bias +fp32 residual -> fp32 (fc2->out)
template <int EPI>
__global__ void __launch_bounds__(256) gemm_mma(
    const __nv_bfloat16* __restrict__ A, const __nv_bfloat16* __restrict__ Bt,
    const float* __restrict__ bias, const float* __restrict__ add,
    void* __restrict__ Cout, int M, int N, int K)
{
    extern __shared__ __align__(16) __nv_bfloat16 smem[];
    __nv_bfloat16* Asm = smem;                  // 2 stages BM x PITCH
    __nv_bfloat16* Bsm = smem + 2 * A_STAGE;    // 2 stages BN x PITCH

    const int tid  = threadIdx.x;
    const int wid  = tid >> 5;
    const int lane = tid & 31;
    const int wm   = wid >> 2;          // 0..1
    const int wn   = wid & 3;           // 0..3
    const int lr   = lane >> 2;         // 0..7
    const int lc   = lane & 3;          // 0..3
    const int bm   = blockIdx.x * BM;
    const int bn   = blockIdx.y * BN;
    const int nk   = K / BK;

    float acc[4][3][4];
#pragma unroll
    for (int i = 0; i < 4; i++)
#pragma unroll
        for (int j = 0; j < 3; j++)
#pragma unroll
            for (int q = 0; q < 4; q++) acc[i][j][q] = 0.f;

    uint32_t asb = smem_u32(Asm);
    uint32_t bsb = smem_u32(Bsm);

    auto load_tile = [&](int k0, int st) {
        // A: 128 rows x 128B = 1024 chunks of 16B (4/thread)
#pragma unroll
        for (int i = tid; i < 1024; i += 256) {
            int m   = i >> 3;
            int k16 = i & 7;
            const __nv_bfloat16* src = A + (size_t)(bm + m) * K + k0 * BK + k16 * 8;
            uint32_t dst = asb + (uint32_t)(st * A_STAGE + m * PITCH + k16 * 8) * 2;
            CP_ASYNC16(dst, src);
        }
        // B: 96 rows x 128B = 768 chunks (3/thread)
#pragma unroll
        for (int i = tid; i < 768; i += 256) {
            int n   = i >> 3;
            int k16 = i & 7;
            const __nv_bfloat16* src = Bt + (size_t)(bn + n) * K + k0 * BK + k16 * 8;
            uint32_t dst = bsb + (uint32_t)(st * B_STAGE + n * PITCH + k16 * 8) * 2;
            CP_ASYNC16(dst, src);
        }
        CP_ASYNC_COMMIT();
    };

    load_tile(0, 0);

    for (int k0 = 0; k0 < nk; k0++) {
        if (k0 + 1 < nk) { load_tile(k0 + 1, (k0 + 1) & 1); CP_ASYNC_WAIT_1(); }
        else             { CP_ASYNC_WAIT_0(); }
        __syncthreads();

        const uint32_t* As32 = (const uint32_t*)(Asm + (size_t)(k0 & 1) * A_STAGE);
        const uint32_t* Bs32 = (const uint32_t*)(Bsm + (size_t)(k0 & 1) * B_STAGE);
#pragma unroll
        for (int ks = 0; ks < 4; ks++) {        // 4 x k16 per BK=64
            uint32_t a[4][4];
#pragma unroll
            for (int mi = 0; mi < 4; mi++) {
                int m = wm * 64 + mi * 16 + lr;
                a[mi][0] = As32[m * WPITCH + ks * 8 + lc];
                a[mi][1] = As32[(m + 8) * WPITCH + ks * 8 + lc];
                a[mi][2] = As32[m * WPITCH + ks * 8 + lc + 4];
                a[mi][3] = As32[(m + 8) * WPITCH + ks * 8 + lc + 4];
            }
            uint32_t b[3][2];
#pragma unroll
            for (int ni = 0; ni < 3; ni++) {
                int n = wn * 24 + ni * 8 + lr;
                b[ni][0] = Bs32[n * WPITCH + ks * 8 + lc];
                b[ni][1] = Bs32[n * WPITCH + ks * 8 + lc + 4];
            }
#pragma unroll
            for (int mi = 0; mi < 4; mi++)
#pragma unroll
                for (int ni = 0; ni < 3; ni++)
                    mma_bf16(acc[mi][ni], a[mi], b[ni]);
        }
        __syncthreads();
    }

#pragma unroll
    for (int mi = 0; mi < 4; mi++) {
#pragma unroll
        for (int half = 0; half < 2; half++) {
            int row = bm + wm * 64 + mi * 16 + lr + half * 8;
            int orow = row;
            if (EPI == 1) {
                int win = row / N_, n = row - win * N_;
                int b = win >> 6, wl = win & 63;
                int hs = (wl >> 3) * WS_ + n / WS_;
                int ws = (wl & 7) * WS_ + (n - (n / WS_) * WS_);
                int h = hs + SS_; if (h >= H_) h -= H_;
                int w = ws + SS_; if (w >= W_) w -= W_;
                orow = (b * H_ + h) * W_ + w;
            }
#pragma unroll
            for (int ni = 0; ni < 3; ni++) {
                int c = bn + wn * 24 + ni * 8 + 2 * lc;
                float2 bv = *(const float2*)(bias + c);
                float vx = acc[mi][ni][half * 2 + 0] + bv.x;
                float vy = acc[mi][ni][half * 2 + 1] + bv.y;
                if (EPI == 1) {
                    float2 av = *(const float2*)(add + (size_t)orow * N + c);
                    vx += av.x; vy += av.y;
                }
                if (EPI == 2) { vx *= normcdff(vx); vy *= normcdff(vy); }
                if (EPI == 3) {
                    float2 av = *(const float2*)(add + (size_t)row * N + c);
                    vx += av.x; vy += av.y;
                }
                if (EPI == 0 || EPI == 2) {
                    __nv_bfloat16* Co = (__nv_bfloat16*)Cout;
                    *(__nv_bfloat162*)(Co + (size_t)orow * N + c) =
                        __floats2bfloat162_rn(vx, vy);
                } else {
                    float* Co = (float*)Cout;
                    *(float2*)(Co + (size_t)orow * N + c) = make_float2(vx, vy);
                }
            }
        }
    }
}

// ---------------------------------------------------------------- attention
// One block per (window, head), 128 threads. bf16 in (g_qkv), bf16 out (g_attno),
// fp32 math in smem/registers.
__global__ void __launch_bounds__(128) attn_kernel(
    const float* __restrict__ rpb, const float* __restrict__ mask)
{
    int win  = blockIdx.x;
    int head = blockIdx.y;
    int tid  = threadIdx.x;

    __shared__ __align__(16) float qs[N_][34];
    __shared__ __align__(16) float kT[HD_][50];
    __shared__ __align__(16) float vs[N_][HD_];
    __shared__ __align__(16) float sc[N_][50];
    __shared__ __align__(16) float rpbs[169];

    const __nv_bfloat16* base = g_qkv + (size_t)win * N_ * C3 + head * HD_;
    const float scale = 0.17677669529663687f;

    for (int idx = tid; idx < N_ * HD_; idx += 128) {
        int n = idx >> 5, d = idx & 31;
        const __nv_bfloat16* row = base + (size_t)n * C3 + d;
        qs[n][d] = __bfloat162float(row[0]) * scale;
        kT[d][n] = __bfloat162float(row[C_]);
        vs[n][d] = __bfloat162float(row[2 * C_]);
    }
    for (int idx = tid; idx < 169; idx += 128)
        rpbs[idx] = rpb[idx * NH_ + head];
    __syncthreads();

    const float* mrow = mask + (size_t)(win & (NW_ - 1)) * N_ * N_;
    for (int cell = tid; cell < 175; cell += 128) {
        int ng = cell / 25;
        int m2 = cell - ng * 25;
        int m  = m2 * 2;
        float acc[7][2];
#pragma unroll
        for (int j = 0; j < 7; j++) { acc[j][0] = 0.f; acc[j][1] = 0.f; }
#pragma unroll
        for (int d = 0; d < HD_; d += 2) {
            float2 k0 = *(const float2*)&kT[d][m];
            float2 k1 = *(const float2*)&kT[d + 1][m];
#pragma unroll
            for (int j = 0; j < 7; j++) {
                float2 qv = *(const float2*)&qs[ng * 7 + j][d];
                acc[j][0] += qv.x * k0.x + qv.y * k1.x;
                acc[j][1] += qv.x * k0.y + qv.y * k1.y;
            }
        }
        int i2 = m / WS_, j2 = m - i2 * WS_;
        int i2b = (m + 1) / WS_, j2b = (m + 1) - i2b * WS_;
#pragma unroll
        for (int j = 0; j < 7; j++) {
            int n = ng * 7 + j;
            int i1 = n / WS_, j1 = n - i1 * WS_;
            int rel0 = (i1 - i2 + WS_ - 1) * (2 * WS_ - 1) + (j1 - j2 + WS_ - 1);
            sc[n][m] = acc[j][0] + rpbs[rel0] + mrow[n * N_ + m];
            if (m + 1 < N_) {
                int rel1 = (i1 - i2b + WS_ - 1) * (2 * WS_ - 1) + (j1 - j2b + WS_ - 1);
                sc[n][m + 1] = acc[j][1] + rpbs[rel1] + mrow[n * N_ + m + 1];
            }
        }
    }
    __syncthreads();

    int warp = tid >> 5, lane = tid & 31;
    for (int n = warp; n < N_; n += 4) {
        float v0 = (lane < N_)      ? sc[n][lane]      : -1e30f;
        float v1 = (lane + 32 < N_) ? sc[n][lane + 32] : -1e30f;
        float mx = fmaxf(v0, v1);
#pragma unroll
        for (int o = 16; o; o >>= 1) mx = fmaxf(mx, __shfl_xor_sync(0xffffffffu, mx, o));
        float e0 = (lane < N_)      ? __expf(v0 - mx) : 0.f;
        float e1 = (lane + 32 < N_) ? __expf(v1 - mx) : 0.f;
        float s = e0 + e1;
#pragma unroll
        for (int o = 16; o; o >>= 1) s += __shfl_xor_sync(0xffffffffu, s, o);
        float inv = 1.f / s;
        if (lane < N_)      sc[n][lane]      = e0 * inv;
        if (lane + 32 < N_) sc[n][lane + 32] = e1 * inv;
    }
    __syncthreads();

    if (tid < 104) {
        int ngb = tid >> 3;
        int d   = (tid & 7) * 4;
        float acc[4][4];
#pragma unroll
        for (int i = 0; i < 4; i++)
#pragma unroll
            for (int q = 0; q < 4; q++) acc[i][q] = 0.f;

        for (int m = 0; m < N_; m++) {
            float4 vv = *(const float4*)&vs[m][d];
#pragma unroll
            for (int i = 0; i < 4; i++) {
                int n = ngb * 4 + i;
                float p = (n < N_) ? sc[n][m] : 0.f;
                acc[i][0] += p * vv.x;
                acc[i][1] += p * vv.y;
                acc[i][2] += p * vv.z;
                acc[i][3] += p * vv.w;
            }
        }
        __nv_bfloat16* ob = g_attno + (size_t)win * N_ * C_ + head * HD_;
#pragma unroll
        for (int i = 0; i < 4; i++) {
            int n = ngb * 4 + i;
            if (n < N_) {
                __nv_bfloat162* p = (__nv_bfloat162*)(ob + (size_t)n * C_ + d);
                p[0] = __floats2bfloat162_rn(acc[i][0], acc[i][1]);
                p[1] = __floats2bfloat162_rn(acc[i][2], acc[i][3]);
            }
        }
    }
}

// ----------------------------------------------------------------
extern "C" void kernel_launch(void* const* d_in, const int* in_sizes, int n_in,
                              void* d_out, int out_size)
{
    const float* x     = (const float*)d_in[0];
    const float* mask  = (const float*)d_in[1];
    const float* ln1g  = (const float*)d_in[2];
    const float* ln1b  = (const float*)d_in[3];
    const float* qkvw  = (const float*)d_in[4];
    const float* qkvb  = (const float*)d_in[5];
    const float* rpb   = (const float*)d_in[6];
    const float* projw = (const float*)d_in[7];
    const float* projb = (const float*)d_in[8];
    const float* ln2g  = (const float*)d_in[9];
    const float* ln2b  = (const float*)d_in[10];
    const float* fc1w  = (const float*)d_in[11];
    const float* fc1b  = (const float*)d_in[12];
    const float* fc2w  = (const float*)d_in[13];
    const float* fc2b  = (const float*)d_in[14];
    float* out = (float*)d_out;

    __nv_bfloat16 *hwin, *qkv, *attno, *ln2, *hid;
    __nv_bfloat16 *qkvwT, *projT, *fc1T, *fc2T;
    float *x1;
    cudaGetSymbolAddress((void**)&hwin,  g_hwin);
    cudaGetSymbolAddress((void**)&qkv,   g_qkv);
    cudaGetSymbolAddress((void**)&attno, g_attno);
    cudaGetSymbolAddress((void**)&x1,    g_x1);
    cudaGetSymbolAddress((void**)&ln2,   g_ln2);
    cudaGetSymbolAddress((void**)&hid,   g_hid);
    cudaGetSymbolAddress((void**)&qkvwT, g_qkvwT);
    cudaGetSymbolAddress((void**)&projT, g_projT);
    cudaGetSymbolAddress((void**)&fc1T,  g_fc1T);
    cudaGetSymbolAddress((void**)&fc2T,  g_fc2T);

    cudaFuncSetAttribute(gemm_mma<0>, cudaFuncAttributeMaxDynamicSharedMemorySize, SMEM_BYTES);
    cudaFuncSetAttribute(gemm_mma<1>, cudaFuncAttributeMaxDynamicSharedMemorySize, SMEM_BYTES);
    cudaFuncSetAttribute(gemm_mma<2>, cudaFuncAttributeMaxDynamicSharedMemorySize, SMEM_BYTES);
    cudaFuncSetAttribute(gemm_mma<3>, cudaFuncAttributeMaxDynamicSharedMemorySize, SMEM_BYTES);

    // 0) Weight convert + transpose ([K][N] fp32 -> [N][K] bf16)
    wprep_kernel<<<dim3(C_ / 32, C3 / 32),   dim3(32, 8)>>>(qkvw,  qkvwT, C_, C3);
    wprep_kernel<<<dim3(C_ / 32, C_ / 32),   dim3(32, 8)>>>(projw, projT, C_, C_);
    wprep_kernel<<<dim3(C_ / 32, HID_ / 32), dim3(32, 8)>>>(fc1w,  fc1T,  C_, HID_);
    wprep_kernel<<<dim3(HID_ / 32, C_ / 32), dim3(32, 8)>>>(fc2w,  fc2T,  HID_, C_);

    const int ln_grid = TOK / 8;

    // 1) LN1 + shift + window partition -> bf16
    ln_kernel<1><<<ln_grid, 256>>>(x, hwin, ln1g, ln1b);

    // 2) QKV GEMM -> bf16
    gemm_mma<0><<<dim3(TOK / BM, C3 / BN), 256, SMEM_BYTES>>>(
        hwin, qkvwT, qkvb, nullptr, qkv, TOK, C3, C_);

    // 3) Windowed attention -> bf16
    attn_kernel<<<dim3(WINS, NH_), 128>>>(rpb, mask);

    // 4) proj + window reverse + fp32 residual -> x1 (fp32)
    gemm_mma<1><<<dim3(TOK / BM, C_ / BN), 256, SMEM_BYTES>>>(
        attno, projT, projb, x, x1, TOK, C_, C_);

    // 5) LN2 -> bf16
    ln_kernel<0><<<ln_grid, 256>>>(x1, ln2, ln2g, ln2b);

    // 6) FC1 + GELU -> bf16
    gemm_mma<2><<<dim3(TOK / BM, HID_ / BN), 256, SMEM_BYTES>>>(
        ln2, fc1T, fc1b, nullptr, hid, TOK, HID_, C_);

    // 7) FC2 + fp32 residual -> out (fp32)
    gemm_mma<3><<<dim3(TOK / BM, C_ / BN), 256, SMEM_BYTES>>>(
        hid, fc2T, fc2b, x1, out, TOK, C_, HID_);
}

// round 9
// speedup vs baseline: 1.5276x; 1.0117x over previous
#include <cuda_runtime.h>
#include <cuda_bf16.h>
#include <cstdint>
#include <math.h>

// ---------------------------------------------------------------- constants
constexpr int B_   = 32;
constexpr int H_   = 56;
constexpr int W_   = 56;
constexpr int C_   = 192;
constexpr int NH_  = 6;
constexpr int WS_  = 7;
constexpr int SS_  = 3;
constexpr int N_   = 49;
constexpr int HD_  = 32;
constexpr int NWH  = 8;
constexpr int NW_  = 64;
constexpr int HID_ = 768;
constexpr int TOK  = B_ * H_ * W_;   // 100352
constexpr int WINS = B_ * NW_;       // 2048
constexpr int C3   = 3 * C_;         // 576

// GEMM tiling (mma.sync m16n8k16 bf16): 128x96 CTA, 64x24 warp tile, BK=64
constexpr int BM = 128;
constexpr int BN = 96;
constexpr int BK = 64;               // bf16 elements = 128B per row
constexpr int PITCH = 72;            // bf16 units per smem row (64 + 8 pad)
constexpr int A_STAGE = BM * PITCH;  // bf16 units
constexpr int B_STAGE = BN * PITCH;
constexpr int SMEM_BYTES = 2 * (A_STAGE + B_STAGE) * 2;   // 64512

// ---------------------------------------------------------------- scratch
__device__ __nv_bfloat16 g_hwin[(size_t)TOK * C_];
__device__ __nv_bfloat16 g_qkv[(size_t)TOK * C3];
__device__ __nv_bfloat16 g_attno[(size_t)TOK * C_];
__device__ float         g_x1[(size_t)TOK * C_];
__device__ __nv_bfloat16 g_ln2[(size_t)TOK * C_];
__device__ __nv_bfloat16 g_hid[(size_t)TOK * HID_];
// weights, converted to bf16 and transposed to [N][K]
__device__ __nv_bfloat16 g_qkvwT[(size_t)C3 * C_];
__device__ __nv_bfloat16 g_projT[(size_t)C_ * C_];
__device__ __nv_bfloat16 g_fc1T[(size_t)HID_ * C_];
__device__ __nv_bfloat16 g_fc2T[(size_t)C_ * HID_];

// ---------------------------------------------------------------- helpers
__device__ __forceinline__ uint32_t smem_u32(const void* p) {
    uint32_t a;
    asm("{ .reg .u64 t; cvta.to.shared.u64 t, %1; cvt.u32.u64 %0, t; }"
        : "=r"(a) : "l"(p));
    return a;
}
#define CP_ASYNC16(dst_u32, src_ptr) \
    asm volatile("cp.async.ca.shared.global [%0], [%1], 16;" \
        :: "r"(dst_u32), "l"(src_ptr) : "memory")
#define CP_ASYNC_COMMIT() asm volatile("cp.async.commit_group;" ::: "memory")
#define CP_ASYNC_WAIT_1() asm volatile("cp.async.wait_group 1;" ::: "memory")
#define CP_ASYNC_WAIT_0() asm volatile("cp.async.wait_group 0;" ::: "memory")

__device__ __forceinline__ void mma_bf16(
    float* d, const uint32_t* a, const uint32_t* b)
{
    asm volatile(
        "mma.sync.aligned.m16n8k16.row.col.f32.bf16.bf16.f32 "
        "{%0,%1,%2,%3}, {%4,%5,%6,%7}, {%8,%9}, {%0,%1,%2,%3};"
        : "+f"(d[0]), "+f"(d[1]), "+f"(d[2]), "+f"(d[3])
        : "r"(a[0]), "r"(a[1]), "r"(a[2]), "r"(a[3]),
          "r"(b[0]), "r"(b[1]));
}
__device__ __forceinline__ void ldsm_x4(uint32_t* r, uint32_t addr) {
    asm volatile("ldmatrix.sync.aligned.m8n8.x4.shared.b16 {%0,%1,%2,%3}, [%4];"
        : "=r"(r[0]), "=r"(r[1]), "=r"(r[2]), "=r"(r[3]) : "r"(addr));
}
__device__ __forceinline__ void ldsm_x2(uint32_t* r, uint32_t addr) {
    asm volatile("ldmatrix.sync.aligned.m8n8.x2.shared.b16 {%0,%1}, [%2];"
        : "=r"(r[0]), "=r"(r[1]) : "r"(addr));
}

// --------------------------------------------- weight convert + transpose
// src fp32 [K][N] -> dst bf16 [N][K]
__global__ void wprep_kernel(const float* __restrict__ src,
                             __nv_bfloat16* __restrict__ dst, int K, int N)
{
    __shared__ float t[32][33];
    int kb = blockIdx.x * 32, nb = blockIdx.y * 32;
    int x = threadIdx.x, y = threadIdx.y;      // 32 x 8
    for (int i = y; i < 32; i += 8)
        t[i][x] = src[(size_t)(kb + i) * N + nb + x];
    __syncthreads();
    for (int i = y; i < 32; i += 8)
        dst[(size_t)(nb + i) * K + kb + x] = __float2bfloat16_rn(t[x][i]);
}

// ---------------------------------------------------------------- LayerNorm
template <int PART>
__global__ void __launch_bounds__(256) ln_kernel(
    const float* __restrict__ src, __nv_bfloat16* __restrict__ dst,
    const float* __restrict__ gamma, const float* __restrict__ beta)
{
    int warp = threadIdx.x >> 5;
    int lane = threadIdx.x & 31;
    int t = blockIdx.x * 8 + warp;
    if (t >= TOK) return;

    const float* xr = src + (size_t)t * C_;
    float v[6];
    float s = 0.f;
#pragma unroll
    for (int i = 0; i < 6; i++) { v[i] = xr[lane + 32 * i]; s += v[i]; }
#pragma unroll
    for (int o = 16; o; o >>= 1) s += __shfl_xor_sync(0xffffffffu, s, o);
    float mean = s * (1.f / 192.f);
    float ss = 0.f;
#pragma unroll
    for (int i = 0; i < 6; i++) { float d = v[i] - mean; ss += d * d; }
#pragma unroll
    for (int o = 16; o; o >>= 1) ss += __shfl_xor_sync(0xffffffffu, ss, o);
    float rstd = rsqrtf(ss * (1.f / 192.f) + 1e-5f);

    int dt = t;
    if (PART) {
        int bb = t / (H_ * W_);
        int rem = t - bb * (H_ * W_);
        int h = rem / W_, w = rem - (rem / W_) * W_;
        int hs = h - SS_; if (hs < 0) hs += H_;
        int ws = w - SS_; if (ws < 0) ws += W_;
        int wl = (hs / WS_) * NWH + (ws / WS_);
        int n  = (hs % WS_) * WS_ + (ws % WS_);
        dt = bb * (NW_ * N_) + wl * N_ + n;
    }
    __nv_bfloat16* o = dst + (size_t)dt * C_;
#pragma unroll
    for (int i = 0; i < 6; i++) {
        int c = lane + 32 * i;
        o[c] = __float2bfloat16_rn((v[i] - mean) * rstd * gamma[c] + beta[c]);
    }
}

// ---------------------------------------------------------------- bf16 GEMM
// C[M,N] = A[M,K](bf16) @ Bt[N,K](bf16)^T ; fp32 accum; ldmatrix frag loads.
// EPI 0: +bias -> bf16   EPI 1: +bias +scatter +fp32 residual -> fp32
// EPI 2: gelu(+bias) -> bf16   EPI 3: +bias +fp32 residual -> fp32
template <int EPI>
__global__ void __launch_bounds__(256) gemm_mma(
    const __nv_bfloat16* __restrict__ A, const __nv_bfloat16* __restrict__ Bt,
    const float* __restrict__ bias, const float* __restrict__ add,
    void* __restrict__ Cout, int M, int N, int K)
{
    extern __shared__ __align__(16) __nv_bfloat16 smem[];
    __nv_bfloat16* Asm = smem;                  // 2 stages BM x PITCH
    __nv_bfloat16* Bsm = smem + 2 * A_STAGE;    // 2 stages BN x PITCH

    const int tid  = threadIdx.x;
    const int wid  = tid >> 5;
    const int lane = tid & 31;
    const int wm   = wid >> 2;          // 0..1
    const int wn   = wid & 3;           // 0..3
    const int lr   = lane >> 2;         // 0..7
    const int lc   = lane & 3;          // 0..3
    const int bm   = blockIdx.x * BM;
    const int bn   = blockIdx.y * BN;
    const int nk   = K / BK;

    // ldmatrix per-lane address components
    const int lj   = lane >> 3;         // 0..3 (tile index for x4)
    const int lrow = lane & 7;
    const int a_m  = (lj & 1) * 8 + lrow;     // row within 16-row A tile
    const int a_k  = (lj >> 1) * 8;           // k offset within 16-k tile
    const int b_k  = (lj & 1) * 8;            // x2: lanes 0-7 tile0, 8-15 tile1

    float acc[4][3][4];
#pragma unroll
    for (int i = 0; i < 4; i++)
#pragma unroll
        for (int j = 0; j < 3; j++)
#pragma unroll
            for (int q = 0; q < 4; q++) acc[i][j][q] = 0.f;

    uint32_t asb = smem_u32(Asm);
    uint32_t bsb = smem_u32(Bsm);

    auto load_tile = [&](int k0, int st) {
#pragma unroll
        for (int i = tid; i < 1024; i += 256) {
            int m   = i >> 3;
            int k16 = i & 7;
            const __nv_bfloat16* src = A + (size_t)(bm + m) * K + k0 * BK + k16 * 8;
            uint32_t dst = asb + (uint32_t)(st * A_STAGE + m * PITCH + k16 * 8) * 2;
            CP_ASYNC16(dst, src);
        }
#pragma unroll
        for (int i = tid; i < 768; i += 256) {
            int n   = i >> 3;
            int k16 = i & 7;
            const __nv_bfloat16* src = Bt + (size_t)(bn + n) * K + k0 * BK + k16 * 8;
            uint32_t dst = bsb + (uint32_t)(st * B_STAGE + n * PITCH + k16 * 8) * 2;
            CP_ASYNC16(dst, src);
        }
        CP_ASYNC_COMMIT();
    };

    load_tile(0, 0);

    for (int k0 = 0; k0 < nk; k0++) {
        if (k0 + 1 < nk) { load_tile(k0 + 1, (k0 + 1) & 1); CP_ASYNC_WAIT_1(); }
        else             { CP_ASYNC_WAIT_0(); }
        __syncthreads();

        uint32_t asb_st = asb + (uint32_t)((k0 & 1) * A_STAGE) * 2;
        uint32_t bsb_st = bsb + (uint32_t)((k0 & 1) * B_STAGE) * 2;
#pragma unroll
        for (int ks = 0; ks < 4; ks++) {        // 4 x k16 per BK=64
            uint32_t a[4][4];
#pragma unroll
            for (int mi = 0; mi < 4; mi++) {
                uint32_t addr = asb_st +
                    (uint32_t)((wm * 64 + mi * 16 + a_m) * PITCH + ks * 16 + a_k) * 2;
                ldsm_x4(a[mi], addr);
            }
            uint32_t b[3][2];
#pragma unroll
            for (int ni = 0; ni < 3; ni++) {
                uint32_t addr = bsb_st +
                    (uint32_t)((wn * 24 + ni * 8 + lrow) * PITCH + ks * 16 + b_k) * 2;
                ldsm_x2(b[ni], addr);
            }
#pragma unroll
            for (int mi = 0; mi < 4; mi++)
#pragma unroll
                for (int ni = 0; ni < 3; ni++)
                    mma_bf16(acc[mi][ni], a[mi], b[ni]);
        }
        __syncthreads();
    }

#pragma unroll
    for (int mi = 0; mi < 4; mi++) {
#pragma unroll
        for (int half = 0; half < 2; half++) {
            int row = bm + wm * 64 + mi * 16 + lr + half * 8;
            int orow = row;
            if (EPI == 1) {
                int win = row / N_, n = row - win * N_;
                int b = win >> 6, wl = win & 63;
                int hs = (wl >> 3) * WS_ + n / WS_;
                int ws = (wl & 7) * WS_ + (n - (n / WS_) * WS_);
                int h = hs + SS_; if (h >= H_) h -= H_;
                int w = ws + SS_; if (w >= W_) w -= W_;
                orow = (b * H_ + h) * W_ + w;
            }
#pragma unroll
            for (int ni = 0; ni < 3; ni++) {
                int c = bn + wn * 24 + ni * 8 + 2 * lc;
                float2 bv = *(const float2*)(bias + c);
                float vx = acc[mi][ni][half * 2 + 0] + bv.x;
                float vy = acc[mi][ni][half * 2 + 1] + bv.y;
                if (EPI == 1) {
                    float2 av = *(const float2*)(add + (size_t)orow * N + c);
                    vx += av.x; vy += av.y;
                }
                if (EPI == 2) { vx *= normcdff(vx); vy *= normcdff(vy); }
                if (EPI == 3) {
                    float2 av = *(const float2*)(add + (size_t)row * N + c);
                    vx += av.x; vy += av.y;
                }
                if (EPI == 0 || EPI == 2) {
                    __nv_bfloat16* Co = (__nv_bfloat16*)Cout;
                    *(__nv_bfloat162*)(Co + (size_t)orow * N + c) =
                        __floats2bfloat162_rn(vx, vy);
                } else {
                    float* Co = (float*)Cout;
                    *(float2*)(Co + (size_t)orow * N + c) = make_float2(vx, vy);
                }
            }
        }
    }
}

// ---------------------------------------------------------------- attention
__global__ void __launch_bounds__(128) attn_kernel(
    const float* __restrict__ rpb, const float* __restrict__ mask)
{
    int win  = blockIdx.x;
    int head = blockIdx.y;
    int tid  = threadIdx.x;

    __shared__ __align__(16) float qs[N_][34];
    __shared__ __align__(16) float kT[HD_][50];
    __shared__ __align__(16) float vs[N_][HD_];
    __shared__ __align__(16) float sc[N_][50];
    __shared__ __align__(16) float rpbs[169];

    const __nv_bfloat16* base = g_qkv + (size_t)win * N_ * C3 + head * HD_;
    const float scale = 0.17677669529663687f;

    for (int idx = tid; idx < N_ * HD_; idx += 128) {
        int n = idx >> 5, d = idx & 31;
        const __nv_bfloat16* row = base + (size_t)n * C3 + d;
        qs[n][d] = __bfloat162float(row[0]) * scale;
        kT[d][n] = __bfloat162float(row[C_]);
        vs[n][d] = __bfloat162float(row[2 * C_]);
    }
    for (int idx = tid; idx < 169; idx += 128)
        rpbs[idx] = rpb[idx * NH_ + head];
    __syncthreads();

    const float* mrow = mask + (size_t)(win & (NW_ - 1)) * N_ * N_;
    for (int cell = tid; cell < 175; cell += 128) {
        int ng = cell / 25;
        int m2 = cell - ng * 25;
        int m  = m2 * 2;
        float acc[7][2];
#pragma unroll
        for (int j = 0; j < 7; j++) { acc[j][0] = 0.f; acc[j][1] = 0.f; }
#pragma unroll
        for (int d = 0; d < HD_; d += 2) {
            float2 k0 = *(const float2*)&kT[d][m];
            float2 k1 = *(const float2*)&kT[d + 1][m];
#pragma unroll
            for (int j = 0; j < 7; j++) {
                float2 qv = *(const float2*)&qs[ng * 7 + j][d];
                acc[j][0] += qv.x * k0.x + qv.y * k1.x;
                acc[j][1] += qv.x * k0.y + qv.y * k1.y;
            }
        }
        int i2 = m / WS_, j2 = m - i2 * WS_;
        int i2b = (m + 1) / WS_, j2b = (m + 1) - i2b * WS_;
#pragma unroll
        for (int j = 0; j < 7; j++) {
            int n = ng * 7 + j;
            int i1 = n / WS_, j1 = n - i1 * WS_;
            int rel0 = (i1 - i2 + WS_ - 1) * (2 * WS_ - 1) + (j1 - j2 + WS_ - 1);
            sc[n][m] = acc[j][0] + rpbs[rel0] + mrow[n * N_ + m];
            if (m + 1 < N_) {
                int rel1 = (i1 - i2b + WS_ - 1) * (2 * WS_ - 1) + (j1 - j2b + WS_ - 1);
                sc[n][m + 1] = acc[j][1] + rpbs[rel1] + mrow[n * N_ + m + 1];
            }
        }
    }
    __syncthreads();

    int warp = tid >> 5, lane = tid & 31;
    for (int n = warp; n < N_; n += 4) {
        float v0 = (lane < N_)      ? sc[n][lane]      : -1e30f;
        float v1 = (lane + 32 < N_) ? sc[n][lane + 32] : -1e30f;
        float mx = fmaxf(v0, v1);
#pragma unroll
        for (int o = 16; o; o >>= 1) mx = fmaxf(mx, __shfl_xor_sync(0xffffffffu, mx, o));
        float e0 = (lane < N_)      ? __expf(v0 - mx) : 0.f;
        float e1 = (lane + 32 < N_) ? __expf(v1 - mx) : 0.f;
        float s = e0 + e1;
#pragma unroll
        for (int o = 16; o; o >>= 1) s += __shfl_xor_sync(0xffffffffu, s, o);
        float inv = 1.f / s;
        if (lane < N_)      sc[n][lane]      = e0 * inv;
        if (lane + 32 < N_) sc[n][lane + 32] = e1 * inv;
    }
    __syncthreads();

    if (tid < 104) {
        int ngb = tid >> 3;
        int d   = (tid & 7) * 4;
        float acc[4][4];
#pragma unroll
        for (int i = 0; i < 4; i++)
#pragma unroll
            for (int q = 0; q < 4; q++) acc[i][q] = 0.f;

        for (int m = 0; m < N_; m++) {
            float4 vv = *(const float4*)&vs[m][d];
#pragma unroll
            for (int i = 0; i < 4; i++) {
                int n = ngb * 4 + i;
                float p = (n < N_) ? sc[n][m] : 0.f;
                acc[i][0] += p * vv.x;
                acc[i][1] += p * vv.y;
                acc[i][2] += p * vv.z;
                acc[i][3] += p * vv.w;
            }
        }
        __nv_bfloat16* ob = g_attno + (size_t)win * N_ * C_ + head * HD_;
#pragma unroll
        for (int i = 0; i < 4; i++) {
            int n = ngb * 4 + i;
            if (n < N_) {
                __nv_bfloat162* p = (__nv_bfloat162*)(ob + (size_t)n * C_ + d);
                p[0] = __floats2bfloat162_rn(acc[i][0], acc[i][1]);
                p[1] = __floats2bfloat162_rn(acc[i][2], acc[i][3]);
            }
        }
    }
}

// ----------------------------------------------------------------
extern "C" void kernel_launch(void* const* d_in, const int* in_sizes, int n_in,
                              void* d_out, int out_size)
{
    const float* x     = (const float*)d_in[0];
    const float* mask  = (const float*)d_in[1];
    const float* ln1g  = (const float*)d_in[2];
    const float* ln1b  = (const float*)d_in[3];
    const float* qkvw  = (const float*)d_in[4];
    const float* qkvb  = (const float*)d_in[5];
    const float* rpb   = (const float*)d_in[6];
    const float* projw = (const float*)d_in[7];
    const float* projb = (const float*)d_in[8];
    const float* ln2g  = (const float*)d_in[9];
    const float* ln2b  = (const float*)d_in[10];
    const float* fc1w  = (const float*)d_in[11];
    const float* fc1b  = (const float*)d_in[12];
    const float* fc2w  = (const float*)d_in[13];
    const float* fc2b  = (const float*)d_in[14];
    float* out = (float*)d_out;

    __nv_bfloat16 *hwin, *qkv, *attno, *ln2, *hid;
    __nv_bfloat16 *qkvwT, *projT, *fc1T, *fc2T;
    float *x1;
    cudaGetSymbolAddress((void**)&hwin,  g_hwin);
    cudaGetSymbolAddress((void**)&qkv,   g_qkv);
    cudaGetSymbolAddress((void**)&attno, g_attno);
    cudaGetSymbolAddress((void**)&x1,    g_x1);
    cudaGetSymbolAddress((void**)&ln2,   g_ln2);
    cudaGetSymbolAddress((void**)&hid,   g_hid);
    cudaGetSymbolAddress((void**)&qkvwT, g_qkvwT);
    cudaGetSymbolAddress((void**)&projT, g_projT);
    cudaGetSymbolAddress((void**)&fc1T,  g_fc1T);
    cudaGetSymbolAddress((void**)&fc2T,  g_fc2T);

    cudaFuncSetAttribute(gemm_mma<0>, cudaFuncAttributeMaxDynamicSharedMemorySize, SMEM_BYTES);
    cudaFuncSetAttribute(gemm_mma<1>, cudaFuncAttributeMaxDynamicSharedMemorySize, SMEM_BYTES);
    cudaFuncSetAttribute(gemm_mma<2>, cudaFuncAttributeMaxDynamicSharedMemorySize, SMEM_BYTES);
    cudaFuncSetAttribute(gemm_mma<3>, cudaFuncAttributeMaxDynamicSharedMemorySize, SMEM_BYTES);

    // 0) Weight convert + transpose ([K][N] fp32 -> [N][K] bf16)
    wprep_kernel<<<dim3(C_ / 32, C3 / 32),   dim3(32, 8)>>>(qkvw,  qkvwT, C_, C3);
    wprep_kernel<<<dim3(C_ / 32, C_ / 32),   dim3(32, 8)>>>(projw, projT, C_, C_);
    wprep_kernel<<<dim3(C_ / 32, HID_ / 32), dim3(32, 8)>>>(fc1w,  fc1T,  C_, HID_);
    wprep_kernel<<<dim3(HID_ / 32, C_ / 32), dim3(32, 8)>>>(fc2w,  fc2T,  HID_, C_);

    const int ln_grid = TOK / 8;

    // 1) LN1 + shift + window partition -> bf16
    ln_kernel<1><<<ln_grid, 256>>>(x, hwin, ln1g, ln1b);

    // 2) QKV GEMM -> bf16
    gemm_mma<0><<<dim3(TOK / BM, C3 / BN), 256, SMEM_BYTES>>>(
        hwin, qkvwT, qkvb, nullptr, qkv, TOK, C3, C_);

    // 3) Windowed attention -> bf16
    attn_kernel<<<dim3(WINS, NH_), 128>>>(rpb, mask);

    // 4) proj + window reverse + fp32 residual -> x1 (fp32)
    gemm_mma<1><<<dim3(TOK / BM, C_ / BN), 256, SMEM_BYTES>>>(
        attno, projT, projb, x, x1, TOK, C_, C_);

    // 5) LN2 -> bf16
    ln_kernel<0><<<ln_grid, 256>>>(x1, ln2, ln2g, ln2b);

    // 6) FC1 + GELU -> bf16
    gemm_mma<2><<<dim3(TOK / BM, HID_ / BN), 256, SMEM_BYTES>>>(
        ln2, fc1T, fc1b, nullptr, hid, TOK, HID_, C_);

    // 7) FC2 + fp32 residual -> out (fp32)
    gemm_mma<3><<<dim3(TOK / BM, C_ / BN), 256, SMEM_BYTES>>>(
        hid, fc2T, fc2b, x1, out, TOK, C_, HID_);
}

// round 10
// speedup vs baseline: 1.5600x; 1.0212x over previous
#include <cuda_runtime.h>
#include <cuda_bf16.h>
#include <cstdint>
#include <math.h>

// ---------------------------------------------------------------- constants
constexpr int B_   = 32;
constexpr int H_   = 56;
constexpr int W_   = 56;
constexpr int C_   = 192;
constexpr int NH_  = 6;
constexpr int WS_  = 7;
constexpr int SS_  = 3;
constexpr int N_   = 49;
constexpr int HD_  = 32;
constexpr int NWH  = 8;
constexpr int NW_  = 64;
constexpr int HID_ = 768;
constexpr int TOK  = B_ * H_ * W_;   // 100352
constexpr int WINS = B_ * NW_;       // 2048
constexpr int C3   = 3 * C_;         // 576

// GEMM tiling (mma.sync m16n8k16 bf16): 128x96 CTA, 64x24 warp tile, BK=64
constexpr int BM = 128;
constexpr int BN = 96;
constexpr int BK = 64;
constexpr int PITCH = 72;
constexpr int A_STAGE = BM * PITCH;
constexpr int B_STAGE = BN * PITCH;
constexpr int SMEM_BYTES = 2 * (A_STAGE + B_STAGE) * 2;   // 64512

// attention smem layout (bf16 units)
constexpr int AQ_P = 40;             // q/k pitch (80B rows, stride 20 words)
constexpr int AP_P = 72;             // P / vT pitch (144B rows, stride 36 words)
constexpr int OFF_QS = 0;            // 64 x 40
constexpr int OFF_KX = 2560;         // 64 x 40
constexpr int OFF_VT = 5120;         // 32 x 72
constexpr int OFF_PS = 7424;         // 64 x 72
constexpr int ATT_BF16 = 12032;      // total bf16 units

// ---------------------------------------------------------------- scratch
__device__ __nv_bfloat16 g_hwin[(size_t)TOK * C_];
__device__ __nv_bfloat16 g_qkv[(size_t)TOK * C3];
__device__ __nv_bfloat16 g_attno[(size_t)TOK * C_];
__device__ float         g_x1[(size_t)TOK * C_];
__device__ __nv_bfloat16 g_ln2[(size_t)TOK * C_];
__device__ __nv_bfloat16 g_hid[(size_t)TOK * HID_];
__device__ __nv_bfloat16 g_qkvwT[(size_t)C3 * C_];
__device__ __nv_bfloat16 g_projT[(size_t)C_ * C_];
__device__ __nv_bfloat16 g_fc1T[(size_t)HID_ * C_];
__device__ __nv_bfloat16 g_fc2T[(size_t)C_ * HID_];

// ---------------------------------------------------------------- helpers
__device__ __forceinline__ uint32_t smem_u32(const void* p) {
    uint32_t a;
    asm("{ .reg .u64 t; cvta.to.shared.u64 t, %1; cvt.u32.u64 %0, t; }"
        : "=r"(a) : "l"(p));
    return a;
}
#define CP_ASYNC16(dst_u32, src_ptr) \
    asm volatile("cp.async.ca.shared.global [%0], [%1], 16;" \
        :: "r"(dst_u32), "l"(src_ptr) : "memory")
#define CP_ASYNC_COMMIT() asm volatile("cp.async.commit_group;" ::: "memory")
#define CP_ASYNC_WAIT_1() asm volatile("cp.async.wait_group 1;" ::: "memory")
#define CP_ASYNC_WAIT_0() asm volatile("cp.async.wait_group 0;" ::: "memory")

__device__ __forceinline__ void mma_bf16(
    float* d, const uint32_t* a, const uint32_t* b)
{
    asm volatile(
        "mma.sync.aligned.m16n8k16.row.col.f32.bf16.bf16.f32 "
        "{%0,%1,%2,%3}, {%4,%5,%6,%7}, {%8,%9}, {%0,%1,%2,%3};"
        : "+f"(d[0]), "+f"(d[1]), "+f"(d[2]), "+f"(d[3])
        : "r"(a[0]), "r"(a[1]), "r"(a[2]), "r"(a[3]),
          "r"(b[0]), "r"(b[1]));
}
__device__ __forceinline__ void ldsm_x4(uint32_t* r, uint32_t addr) {
    asm volatile("ldmatrix.sync.aligned.m8n8.x4.shared.b16 {%0,%1,%2,%3}, [%4];"
        : "=r"(r[0]), "=r"(r[1]), "=r"(r[2]), "=r"(r[3]) : "r"(addr));
}
__device__ __forceinline__ void ldsm_x2(uint32_t* r, uint32_t addr) {
    asm volatile("ldmatrix.sync.aligned.m8n8.x2.shared.b16 {%0,%1}, [%2];"
        : "=r"(r[0]), "=r"(r[1]) : "r"(addr));
}

// --------------------------------------------- weight convert + transpose
__global__ void wprep_kernel(const float* __restrict__ src,
                             __nv_bfloat16* __restrict__ dst, int K, int N)
{
    __shared__ float t[32][33];
    int kb = blockIdx.x * 32, nb = blockIdx.y * 32;
    int x = threadIdx.x, y = threadIdx.y;
    for (int i = y; i < 32; i += 8)
        t[i][x] = src[(size_t)(kb + i) * N + nb + x];
    __syncthreads();
    for (int i = y; i < 32; i += 8)
        dst[(size_t)(nb + i) * K + kb + x] = __float2bfloat16_rn(t[x][i]);
}

// ---------------------------------------------------------------- LayerNorm
template <int PART>
__global__ void __launch_bounds__(256) ln_kernel(
    const float* __restrict__ src, __nv_bfloat16* __restrict__ dst,
    const float* __restrict__ gamma, const float* __restrict__ beta)
{
    int warp = threadIdx.x >> 5;
    int lane = threadIdx.x & 31;
    int t = blockIdx.x * 8 + warp;
    if (t >= TOK) return;

    const float* xr = src + (size_t)t * C_;
    float v[6];
    float s = 0.f;
#pragma unroll
    for (int i = 0; i < 6; i++) { v[i] = xr[lane + 32 * i]; s += v[i]; }
#pragma unroll
    for (int o = 16; o; o >>= 1) s += __shfl_xor_sync(0xffffffffu, s, o);
    float mean = s * (1.f / 192.f);
    float ss = 0.f;
#pragma unroll
    for (int i = 0; i < 6; i++) { float d = v[i] - mean; ss += d * d; }
#pragma unroll
    for (int o = 16; o; o >>= 1) ss += __shfl_xor_sync(0xffffffffu, ss, o);
    float rstd = rsqrtf(ss * (1.f / 192.f) + 1e-5f);

    int dt = t;
    if (PART) {
        int bb = t / (H_ * W_);
        int rem = t - bb * (H_ * W_);
        int h = rem / W_, w = rem - (rem / W_) * W_;
        int hs = h - SS_; if (hs < 0) hs += H_;
        int ws = w - SS_; if (ws < 0) ws += W_;
        int wl = (hs / WS_) * NWH + (ws / WS_);
        int n  = (hs % WS_) * WS_ + (ws % WS_);
        dt = bb * (NW_ * N_) + wl * N_ + n;
    }
    __nv_bfloat16* o = dst + (size_t)dt * C_;
#pragma unroll
    for (int i = 0; i < 6; i++) {
        int c = lane + 32 * i;
        o[c] = __float2bfloat16_rn((v[i] - mean) * rstd * gamma[c] + beta[c]);
    }
}

// ---------------------------------------------------------------- bf16 GEMM
template <int EPI>
__global__ void __launch_bounds__(256) gemm_mma(
    const __nv_bfloat16* __restrict__ A, const __nv_bfloat16* __restrict__ Bt,
    const float* __restrict__ bias, const float* __restrict__ add,
    void* __restrict__ Cout, int M, int N, int K)
{
    extern __shared__ __align__(16) __nv_bfloat16 smem[];
    __nv_bfloat16* Asm = smem;
    __nv_bfloat16* Bsm = smem + 2 * A_STAGE;

    const int tid  = threadIdx.x;
    const int wid  = tid >> 5;
    const int lane = tid & 31;
    const int wm   = wid >> 2;
    const int wn   = wid & 3;
    const int lr   = lane >> 2;
    const int lc   = lane & 3;
    const int bm   = blockIdx.x * BM;
    const int bn   = blockIdx.y * BN;
    const int nk   = K / BK;

    const int lj   = lane >> 3;
    const int lrow = lane & 7;
    const int a_m  = (lj & 1) * 8 + lrow;
    const int a_k  = (lj >> 1) * 8;
    const int b_k  = (lj & 1) * 8;

    float acc[4][3][4];
#pragma unroll
    for (int i = 0; i < 4; i++)
#pragma unroll
        for (int j = 0; j < 3; j++)
#pragma unroll
            for (int q = 0; q < 4; q++) acc[i][j][q] = 0.f;

    uint32_t asb = smem_u32(Asm);
    uint32_t bsb = smem_u32(Bsm);

    auto load_tile = [&](int k0, int st) {
#pragma unroll
        for (int i = tid; i < 1024; i += 256) {
            int m   = i >> 3;
            int k16 = i & 7;
            const __nv_bfloat16* src = A + (size_t)(bm + m) * K + k0 * BK + k16 * 8;
            uint32_t dst = asb + (uint32_t)(st * A_STAGE + m * PITCH + k16 * 8) * 2;
            CP_ASYNC16(dst, src);
        }
#pragma unroll
        for (int i = tid; i < 768; i += 256) {
            int n   = i >> 3;
            int k16 = i & 7;
            const __nv_bfloat16* src = Bt + (size_t)(bn + n) * K + k0 * BK + k16 * 8;
            uint32_t dst = bsb + (uint32_t)(st * B_STAGE + n * PITCH + k16 * 8) * 2;
            CP_ASYNC16(dst, src);
        }
        CP_ASYNC_COMMIT();
    };

    load_tile(0, 0);

    for (int k0 = 0; k0 < nk; k0++) {
        if (k0 + 1 < nk) { load_tile(k0 + 1, (k0 + 1) & 1); CP_ASYNC_WAIT_1(); }
        else             { CP_ASYNC_WAIT_0(); }
        __syncthreads();

        uint32_t asb_st = asb + (uint32_t)((k0 & 1) * A_STAGE) * 2;
        uint32_t bsb_st = bsb + (uint32_t)((k0 & 1) * B_STAGE) * 2;
#pragma unroll
        for (int ks = 0; ks < 4; ks++) {
            uint32_t a[4][4];
#pragma unroll
            for (int mi = 0; mi < 4; mi++) {
                uint32_t addr = asb_st +
                    (uint32_t)((wm * 64 + mi * 16 + a_m) * PITCH + ks * 16 + a_k) * 2;
                ldsm_x4(a[mi], addr);
            }
            uint32_t b[3][2];
#pragma unroll
            for (int ni = 0; ni < 3; ni++) {
                uint32_t addr = bsb_st +
                    (uint32_t)((wn * 24 + ni * 8 + lrow) * PITCH + ks * 16 + b_k) * 2;
                ldsm_x2(b[ni], addr);
            }
#pragma unroll
            for (int mi = 0; mi < 4; mi++)
#pragma unroll
                for (int ni = 0; ni < 3; ni++)
                    mma_bf16(acc[mi][ni], a[mi], b[ni]);
        }
        __syncthreads();
    }

#pragma unroll
    for (int mi = 0; mi < 4; mi++) {
#pragma unroll
        for (int half = 0; half < 2; half++) {
            int row = bm + wm * 64 + mi * 16 + lr + half * 8;
            int orow = row;
            if (EPI == 1) {
                int win = row / N_, n = row - win * N_;
                int b = win >> 6, wl = win & 63;
                int hs = (wl >> 3) * WS_ + n / WS_;
                int ws = (wl & 7) * WS_ + (n - (n / WS_) * WS_);
                int h = hs + SS_; if (h >= H_) h -= H_;
                int w = ws + SS_; if (w >= W_) w -= W_;
                orow = (b * H_ + h) * W_ + w;
            }
#pragma unroll
            for (int ni = 0; ni < 3; ni++) {
                int c = bn + wn * 24 + ni * 8 + 2 * lc;
                float2 bv = *(const float2*)(bias + c);
                float vx = acc[mi][ni][half * 2 + 0] + bv.x;
                float vy = acc[mi][ni][half * 2 + 1] + bv.y;
                if (EPI == 1) {
                    float2 av = *(const float2*)(add + (size_t)orow * N + c);
                    vx += av.x; vy += av.y;
                }
                if (EPI == 2) { vx *= normcdff(vx); vy *= normcdff(vy); }
                if (EPI == 3) {
                    float2 av = *(const float2*)(add + (size_t)row * N + c);
                    vx += av.x; vy += av.y;
                }
                if (EPI == 0 || EPI == 2) {
                    __nv_bfloat16* Co = (__nv_bfloat16*)Cout;
                    *(__nv_bfloat162*)(Co + (size_t)orow * N + c) =
                        __floats2bfloat162_rn(vx, vy);
                } else {
                    float* Co = (float*)Cout;
                    *(float2*)(Co + (size_t)orow * N + c) = make_float2(vx, vy);
                }
            }
        }
    }
}

// ---------------------------------------------------------------- attention
// One block per (window, head), 128 threads = 4 warps.  Both matmuls on
// bf16 mma.sync (padded 49->64).  Scores staged fp32; softmax applies
// scale + RPB + mask at read time; P rounded to bf16 for the PV MMA.
__global__ void __launch_bounds__(128) attn_kernel(
    const float* __restrict__ rpb, const float* __restrict__ mask)
{
    int win  = blockIdx.x;
    int head = blockIdx.y;
    int tid  = threadIdx.x;
    int warp = tid >> 5;
    int lane = tid & 31;

    __shared__ __align__(16) __nv_bfloat16 ab[ATT_BF16];
    __shared__ __align__(16) float sc[64][52];
    __shared__ __align__(16) float rpbs[169];

    // zero the bf16 arena (padding rows/cols must be 0)
    uint32_t* abw = (uint32_t*)ab;
    for (int i = tid; i < ATT_BF16 / 2; i += 128) abw[i] = 0u;

    const __nv_bfloat16* base = g_qkv + (size_t)win * N_ * C3 + head * HD_;
    for (int idx = tid; idx < 169; idx += 128)
        rpbs[idx] = rpb[idx * NH_ + head];
    __syncthreads();

    // load q, k, vT (raw bf16 copies; scale folded into softmax)
    for (int idx = tid; idx < N_ * HD_; idx += 128) {
        int n = idx >> 5, d = idx & 31;
        const __nv_bfloat16* row = base + (size_t)n * C3 + d;
        ab[OFF_QS + n * AQ_P + d] = row[0];
        ab[OFF_KX + n * AQ_P + d] = row[C_];
        ab[OFF_VT + d * AP_P + n] = row[2 * C_];
    }
    __syncthreads();

    const int lj   = lane >> 3;
    const int lrow = lane & 7;
    const int a_m  = (lj & 1) * 8 + lrow;
    const int a_k  = (lj >> 1) * 8;
    const int b_k  = (lj & 1) * 8;
    const int lr   = lane >> 2;
    const int lc   = lane & 3;

    uint32_t qsb = smem_u32(ab + OFF_QS);
    uint32_t kxb = smem_u32(ab + OFF_KX);
    uint32_t vtb = smem_u32(ab + OFF_VT);
    uint32_t psb = smem_u32(ab + OFF_PS);

    // ---- QK^T: each warp computes rows [warp*16, warp*16+16) x 64 cols
    {
        float c[8][4];
#pragma unroll
        for (int i = 0; i < 8; i++)
#pragma unroll
            for (int q = 0; q < 4; q++) c[i][q] = 0.f;
#pragma unroll
        for (int ks = 0; ks < 2; ks++) {
            uint32_t a[4];
            ldsm_x4(a, qsb + (uint32_t)((warp * 16 + a_m) * AQ_P + ks * 16 + a_k) * 2);
#pragma unroll
            for (int ni = 0; ni < 8; ni++) {
                uint32_t b[2];
                ldsm_x2(b, kxb + (uint32_t)((ni * 8 + lrow) * AQ_P + ks * 16 + b_k) * 2);
                mma_bf16(c[ni], a, b);
            }
        }
#pragma unroll
        for (int ni = 0; ni < 8; ni++) {
            sc[warp * 16 + lr][ni * 8 + 2 * lc]         = c[ni][0];
            sc[warp * 16 + lr][ni * 8 + 2 * lc + 1]     = c[ni][1];
            sc[warp * 16 + lr + 8][ni * 8 + 2 * lc]     = c[ni][2];
            sc[warp * 16 + lr + 8][ni * 8 + 2 * lc + 1] = c[ni][3];
        }
    }
    __syncthreads();

    // ---- softmax rows (scale + bias + mask applied here); write P as bf16
    const float scale = 0.17677669529663687f;
    const float* mrow = mask + (size_t)(win & (NW_ - 1)) * N_ * N_;
    for (int n = warp; n < N_; n += 4) {
        int i1 = n / WS_, j1 = n - (n / WS_) * WS_;
        float v0 = -1e30f, v1 = -1e30f;
        if (lane < N_) {
            int m = lane;
            int i2 = m / WS_, j2 = m - i2 * WS_;
            int rel = (i1 - i2 + WS_ - 1) * (2 * WS_ - 1) + (j1 - j2 + WS_ - 1);
            v0 = sc[n][m] * scale + rpbs[rel] + mrow[n * N_ + m];
        }
        if (lane + 32 < N_) {
            int m = lane + 32;
            int i2 = m / WS_, j2 = m - i2 * WS_;
            int rel = (i1 - i2 + WS_ - 1) * (2 * WS_ - 1) + (j1 - j2 + WS_ - 1);
            v1 = sc[n][m] * scale + rpbs[rel] + mrow[n * N_ + m];
        }
        float mx = fmaxf(v0, v1);
#pragma unroll
        for (int o = 16; o; o >>= 1) mx = fmaxf(mx, __shfl_xor_sync(0xffffffffu, mx, o));
        float e0 = (lane < N_)      ? __expf(v0 - mx) : 0.f;
        float e1 = (lane + 32 < N_) ? __expf(v1 - mx) : 0.f;
        float s = e0 + e1;
#pragma unroll
        for (int o = 16; o; o >>= 1) s += __shfl_xor_sync(0xffffffffu, s, o);
        float inv = 1.f / s;
        if (lane < N_)
            ab[OFF_PS + n * AP_P + lane]      = __float2bfloat16_rn(e0 * inv);
        if (lane + 32 < N_)
            ab[OFF_PS + n * AP_P + lane + 32] = __float2bfloat16_rn(e1 * inv);
    }
    __syncthreads();

    // ---- PV: rows [warp*16, +16) x 32 d-cols, K = 64 (padded keys are 0)
    {
        float o[4][4];
#pragma unroll
        for (int i = 0; i < 4; i++)
#pragma unroll
            for (int q = 0; q < 4; q++) o[i][q] = 0.f;
#pragma unroll
        for (int ks = 0; ks < 4; ks++) {
            uint32_t a[4];
            ldsm_x4(a, psb + (uint32_t)((warp * 16 + a_m) * AP_P + ks * 16 + a_k) * 2);
#pragma unroll
            for (int ni = 0; ni < 4; ni++) {
                uint32_t b[2];
                ldsm_x2(b, vtb + (uint32_t)((ni * 8 + lrow) * AP_P + ks * 16 + b_k) * 2);
                mma_bf16(o[ni], a, b);
            }
        }
        __nv_bfloat16* ob = g_attno + (size_t)win * N_ * C_ + head * HD_;
#pragma unroll
        for (int ni = 0; ni < 4; ni++) {
#pragma unroll
            for (int half = 0; half < 2; half++) {
                int row = warp * 16 + lr + half * 8;
                if (row < N_) {
                    int col = ni * 8 + 2 * lc;
                    *(__nv_bfloat162*)(ob + (size_t)row * C_ + col) =
                        __floats2bfloat162_rn(o[ni][half * 2], o[ni][half * 2 + 1]);
                }
            }
        }
    }
}

// ----------------------------------------------------------------
extern "C" void kernel_launch(void* const* d_in, const int* in_sizes, int n_in,
                              void* d_out, int out_size)
{
    const float* x     = (const float*)d_in[0];
    const float* mask  = (const float*)d_in[1];
    const float* ln1g  = (const float*)d_in[2];
    const float* ln1b  = (const float*)d_in[3];
    const float* qkvw  = (const float*)d_in[4];
    const float* qkvb  = (const float*)d_in[5];
    const float* rpb   = (const float*)d_in[6];
    const float* projw = (const float*)d_in[7];
    const float* projb = (const float*)d_in[8];
    const float* ln2g  = (const float*)d_in[9];
    const float* ln2b  = (const float*)d_in[10];
    const float* fc1w  = (const float*)d_in[11];
    const float* fc1b  = (const float*)d_in[12];
    const float* fc2w  = (const float*)d_in[13];
    const float* fc2b  = (const float*)d_in[14];
    float* out = (float*)d_out;

    __nv_bfloat16 *hwin, *qkv, *attno, *ln2, *hid;
    __nv_bfloat16 *qkvwT, *projT, *fc1T, *fc2T;
    float *x1;
    cudaGetSymbolAddress((void**)&hwin,  g_hwin);
    cudaGetSymbolAddress((void**)&qkv,   g_qkv);
    cudaGetSymbolAddress((void**)&attno, g_attno);
    cudaGetSymbolAddress((void**)&x1,    g_x1);
    cudaGetSymbolAddress((void**)&ln2,   g_ln2);
    cudaGetSymbolAddress((void**)&hid,   g_hid);
    cudaGetSymbolAddress((void**)&qkvwT, g_qkvwT);
    cudaGetSymbolAddress((void**)&projT, g_projT);
    cudaGetSymbolAddress((void**)&fc1T,  g_fc1T);
    cudaGetSymbolAddress((void**)&fc2T,  g_fc2T);

    cudaFuncSetAttribute(gemm_mma<0>, cudaFuncAttributeMaxDynamicSharedMemorySize, SMEM_BYTES);
    cudaFuncSetAttribute(gemm_mma<1>, cudaFuncAttributeMaxDynamicSharedMemorySize, SMEM_BYTES);
    cudaFuncSetAttribute(gemm_mma<2>, cudaFuncAttributeMaxDynamicSharedMemorySize, SMEM_BYTES);
    cudaFuncSetAttribute(gemm_mma<3>, cudaFuncAttributeMaxDynamicSharedMemorySize, SMEM_BYTES);

    // 0) Weight convert + transpose ([K][N] fp32 -> [N][K] bf16)
    wprep_kernel<<<dim3(C_ / 32, C3 / 32),   dim3(32, 8)>>>(qkvw,  qkvwT, C_, C3);
    wprep_kernel<<<dim3(C_ / 32, C_ / 32),   dim3(32, 8)>>>(projw, projT, C_, C_);
    wprep_kernel<<<dim3(C_ / 32, HID_ / 32), dim3(32, 8)>>>(fc1w,  fc1T,  C_, HID_);
    wprep_kernel<<<dim3(HID_ / 32, C_ / 32), dim3(32, 8)>>>(fc2w,  fc2T,  HID_, C_);

    const int ln_grid = TOK / 8;

    // 1) LN1 + shift + window partition -> bf16
    ln_kernel<1><<<ln_grid, 256>>>(x, hwin, ln1g, ln1b);

    // 2) QKV GEMM -> bf16
    gemm_mma<0><<<dim3(TOK / BM, C3 / BN), 256, SMEM_BYTES>>>(
        hwin, qkvwT, qkvb, nullptr, qkv, TOK, C3, C_);

    // 3) Windowed attention (tensor-core) -> bf16
    attn_kernel<<<dim3(WINS, NH_), 128>>>(rpb, mask);

    // 4) proj + window reverse + fp32 residual -> x1 (fp32)
    gemm_mma<1><<<dim3(TOK / BM, C_ / BN), 256, SMEM_BYTES>>>(
        attno, projT, projb, x, x1, TOK, C_, C_);

    // 5) LN2 -> bf16
    ln_kernel<0><<<ln_grid, 256>>>(x1, ln2, ln2g, ln2b);

    // 6) FC1 + GELU -> bf16
    gemm_mma<2><<<dim3(TOK / BM, HID_ / BN), 256, SMEM_BYTES>>>(
        ln2, fc1T, fc1b, nullptr, hid, TOK, HID_, C_);

    // 7) FC2 + fp32 residual -> out (fp32)
    gemm_mma<3><<<dim3(TOK / BM, C_ / BN), 256, SMEM_BYTES>>>(
        hid, fc2T, fc2b, x1, out, TOK, C_, HID_);
}